// round 3
// baseline (speedup 1.0000x reference)
#include <cuda_runtime.h>
#include <math.h>

#define B_SZ   2
#define S_LEN  2048
#define DM     2048
#define NH     32
#define NKV    8
#define DK     64
#define KVW    (NKV * DK)      // 512
#define MROWS  (B_SZ * S_LEN)  // 4096

// Scratch: device globals (no allocation allowed in kernel_launch)
__device__ float g_Q[MROWS * DM];     // 33.5 MB
__device__ float g_K[MROWS * KVW];    //  8.4 MB
__device__ float g_V[MROWS * KVW];    //  8.4 MB
__device__ float g_C[MROWS * DM];     // 33.5 MB (attention context)

// ---------------------------------------------------------------------------
// SGEMM: C[M,N] = A[M,K] @ B[K,N] + bias[N]
// 128x128 tile, BK=8, 256 threads, 8x8 per thread.
// ---------------------------------------------------------------------------
__global__ __launch_bounds__(256) void sgemm_bias_kernel(
    const float* __restrict__ A, const float* __restrict__ Bm,
    const float* __restrict__ bias, float* __restrict__ C,
    int M, int N, int K)
{
    __shared__ float As[8][128];   // transposed A tile: As[k][m]
    __shared__ float Bs[8][128];   // Bs[k][n]

    const int tid = threadIdx.x;
    const int tx = tid & 15;       // 0..15 -> N
    const int ty = tid >> 4;       // 0..15 -> M
    const int rowBase = blockIdx.y * 128;
    const int colBase = blockIdx.x * 128;

    float acc[8][8];
#pragma unroll
    for (int i = 0; i < 8; i++)
#pragma unroll
        for (int j = 0; j < 8; j++) acc[i][j] = 0.f;

    const int aRow = tid >> 1;           // 0..127
    const int aCol = (tid & 1) * 4;      // 0 or 4
    const int bRow = tid >> 5;           // 0..7
    const int bCol = (tid & 31) * 4;     // 0..124

    const float* Ap = A + (size_t)(rowBase + aRow) * K + aCol;
    const float* Bp = Bm + (size_t)bRow * N + colBase + bCol;

    for (int k0 = 0; k0 < K; k0 += 8) {
        float4 va = *(const float4*)(Ap + k0);
        float4 vb = *(const float4*)(Bp + (size_t)k0 * N);
        As[aCol + 0][aRow] = va.x;
        As[aCol + 1][aRow] = va.y;
        As[aCol + 2][aRow] = va.z;
        As[aCol + 3][aRow] = va.w;
        *(float4*)&Bs[bRow][bCol] = vb;
        __syncthreads();

#pragma unroll
        for (int k = 0; k < 8; k++) {
            float4 a0 = *(const float4*)&As[k][ty * 8];
            float4 a1 = *(const float4*)&As[k][ty * 8 + 4];
            float4 b0 = *(const float4*)&Bs[k][tx * 8];
            float4 b1 = *(const float4*)&Bs[k][tx * 8 + 4];
            float ar[8] = {a0.x, a0.y, a0.z, a0.w, a1.x, a1.y, a1.z, a1.w};
            float br[8] = {b0.x, b0.y, b0.z, b0.w, b1.x, b1.y, b1.z, b1.w};
#pragma unroll
            for (int i = 0; i < 8; i++)
#pragma unroll
                for (int j = 0; j < 8; j++)
                    acc[i][j] = fmaf(ar[i], br[j], acc[i][j]);
        }
        __syncthreads();
    }

    // epilogue: add bias, float4 stores
#pragma unroll
    for (int i = 0; i < 8; i++) {
        size_t r = (size_t)(rowBase + ty * 8 + i);
        float* Crow = C + r * N + colBase + tx * 8;
        const float* brow = bias + colBase + tx * 8;
        float4 v0, v1;
        v0.x = acc[i][0] + brow[0];
        v0.y = acc[i][1] + brow[1];
        v0.z = acc[i][2] + brow[2];
        v0.w = acc[i][3] + brow[3];
        v1.x = acc[i][4] + brow[4];
        v1.y = acc[i][5] + brow[5];
        v1.z = acc[i][6] + brow[6];
        v1.w = acc[i][7] + brow[7];
        *(float4*)(Crow) = v0;
        *(float4*)(Crow + 4) = v1;
    }
}

// ---------------------------------------------------------------------------
// Flash-attention (causal, GQA). One block per (64-row Q tile, head, batch).
// 256 threads: thread (tx,ty) owns a 4x4 micro-tile (ty->q rows, tx->k/d cols).
// Online softmax with 16-lane shfl row reductions.
// ---------------------------------------------------------------------------
#define PITCH 68
#define ATT_SMEM (4 * 64 * PITCH * 4)   // 69632 bytes

__global__ __launch_bounds__(256) void gqa_flash_kernel(
    const float* __restrict__ Q, const float* __restrict__ Kg,
    const float* __restrict__ Vg, float* __restrict__ Og)
{
    extern __shared__ float sm[];
    float* Qt = sm;                   // [d][q]  64 x PITCH
    float* Kt = Qt + 64 * PITCH;      // [d][k]
    float* Vs = Kt + 64 * PITCH;      // [k][d]
    float* Pt = Vs + 64 * PITCH;      // [k][q]

    const int tid = threadIdx.x;
    const int tx = tid & 15;
    const int ty = tid >> 4;
    const int mtile = blockIdx.x;
    const int h = blockIdx.y;
    const int b = blockIdx.z;
    const int kvh = h >> 2;           // 4 query heads per kv head
    const int m0 = mtile * 64;

    const float* Qbase = Q + ((size_t)b * S_LEN + m0) * DM + h * DK;
    const float* Kbase = Kg + (size_t)b * S_LEN * KVW + kvh * DK;
    const float* Vbase = Vg + (size_t)b * S_LEN * KVW + kvh * DK;

    // Load Q tile transposed: Qt[d][q]
#pragma unroll
    for (int t = 0; t < 4; t++) {
        int idx = tid + t * 256;        // 0..1023 float4 slots
        int q = idx >> 4;               // 0..63
        int c = (idx & 15) * 4;         // 0..60
        float4 v = *(const float4*)(Qbase + (size_t)q * DM + c);
        Qt[(c + 0) * PITCH + q] = v.x;
        Qt[(c + 1) * PITCH + q] = v.y;
        Qt[(c + 2) * PITCH + q] = v.z;
        Qt[(c + 3) * PITCH + q] = v.w;
    }

    float m_i[4], l_i[4], acc[4][4];
#pragma unroll
    for (int i = 0; i < 4; i++) {
        m_i[i] = -INFINITY;
        l_i[i] = 0.f;
#pragma unroll
        for (int j = 0; j < 4; j++) acc[i][j] = 0.f;
    }

    for (int jt = 0; jt <= mtile; jt++) {
        __syncthreads();   // prior iter's Pt/Vs reads done before overwrite
        const int k0 = jt * 64;

        // Load K tile (transposed) and V tile
#pragma unroll
        for (int t = 0; t < 4; t++) {
            int idx = tid + t * 256;
            int r = idx >> 4;
            int c = (idx & 15) * 4;
            float4 kv = *(const float4*)(Kbase + (size_t)(k0 + r) * KVW + c);
            Kt[(c + 0) * PITCH + r] = kv.x;
            Kt[(c + 1) * PITCH + r] = kv.y;
            Kt[(c + 2) * PITCH + r] = kv.z;
            Kt[(c + 3) * PITCH + r] = kv.w;
            *(float4*)&Vs[r * PITCH + c] =
                *(const float4*)(Vbase + (size_t)(k0 + r) * KVW + c);
        }
        __syncthreads();

        // S = Q @ K^T
        float s[4][4];
#pragma unroll
        for (int i = 0; i < 4; i++)
#pragma unroll
            for (int j = 0; j < 4; j++) s[i][j] = 0.f;

#pragma unroll 4
        for (int d = 0; d < 64; d++) {
            float4 qv = *(const float4*)&Qt[d * PITCH + ty * 4];
            float4 kv = *(const float4*)&Kt[d * PITCH + tx * 4];
            float qa[4] = {qv.x, qv.y, qv.z, qv.w};
            float ka[4] = {kv.x, kv.y, kv.z, kv.w};
#pragma unroll
            for (int i = 0; i < 4; i++)
#pragma unroll
                for (int j = 0; j < 4; j++)
                    s[i][j] = fmaf(qa[i], ka[j], s[i][j]);
        }

        const float rsc = 0.125f;   // 1/sqrt(64)
        if (jt == mtile) {
            // diagonal tile: mask k > q (tile-local offsets equal since j0==m0)
#pragma unroll
            for (int i = 0; i < 4; i++)
#pragma unroll
                for (int j = 0; j < 4; j++)
                    s[i][j] = (tx * 4 + j > ty * 4 + i) ? -INFINITY : s[i][j] * rsc;
        } else {
#pragma unroll
            for (int i = 0; i < 4; i++)
#pragma unroll
                for (int j = 0; j < 4; j++) s[i][j] *= rsc;
        }

        // Online softmax per q row (reduce across 16 lanes sharing ty)
#pragma unroll
        for (int i = 0; i < 4; i++) {
            float mx = fmaxf(fmaxf(s[i][0], s[i][1]), fmaxf(s[i][2], s[i][3]));
#pragma unroll
            for (int o = 8; o > 0; o >>= 1)
                mx = fmaxf(mx, __shfl_xor_sync(0xffffffffu, mx, o));
            float mnew = fmaxf(m_i[i], mx);
            float corr = __expf(m_i[i] - mnew);
            float ls = 0.f;
#pragma unroll
            for (int j = 0; j < 4; j++) {
                float p = __expf(s[i][j] - mnew);
                s[i][j] = p;
                ls += p;
            }
#pragma unroll
            for (int o = 8; o > 0; o >>= 1)
                ls += __shfl_xor_sync(0xffffffffu, ls, o);
            l_i[i] = l_i[i] * corr + ls;
            m_i[i] = mnew;
#pragma unroll
            for (int j = 0; j < 4; j++) acc[i][j] *= corr;
        }

        // Stage P transposed: Pt[k][q]
#pragma unroll
        for (int i = 0; i < 4; i++)
#pragma unroll
            for (int j = 0; j < 4; j++)
                Pt[(tx * 4 + j) * PITCH + ty * 4 + i] = s[i][j];
        __syncthreads();

        // O += P @ V
#pragma unroll 4
        for (int k = 0; k < 64; k++) {
            float4 pv = *(const float4*)&Pt[k * PITCH + ty * 4];
            float4 vv = *(const float4*)&Vs[k * PITCH + tx * 4];
            float pa[4] = {pv.x, pv.y, pv.z, pv.w};
            float va[4] = {vv.x, vv.y, vv.z, vv.w};
#pragma unroll
            for (int i = 0; i < 4; i++)
#pragma unroll
                for (int j = 0; j < 4; j++)
                    acc[i][j] = fmaf(pa[i], va[j], acc[i][j]);
        }
    }

    // Epilogue: normalize and write context
    float* Ob = Og + ((size_t)b * S_LEN + m0) * DM + h * DK;
#pragma unroll
    for (int i = 0; i < 4; i++) {
        float inv = 1.f / l_i[i];
        float4 o;
        o.x = acc[i][0] * inv;
        o.y = acc[i][1] * inv;
        o.z = acc[i][2] * inv;
        o.w = acc[i][3] * inv;
        *(float4*)(Ob + (size_t)(ty * 4 + i) * DM + tx * 4) = o;
    }
}

// ---------------------------------------------------------------------------
// Launch
// ---------------------------------------------------------------------------
extern "C" void kernel_launch(void* const* d_in, const int* in_sizes, int n_in,
                              void* d_out, int out_size)
{
    (void)in_sizes; (void)n_in; (void)out_size;
    const float* x  = (const float*)d_in[0];
    // d_in[1] = mask (fixed lower-triangular; causality handled in-kernel)
    const float* Wq = (const float*)d_in[2];
    const float* bq = (const float*)d_in[3];
    const float* Wk = (const float*)d_in[4];
    const float* bk = (const float*)d_in[5];
    const float* Wv = (const float*)d_in[6];
    const float* bv = (const float*)d_in[7];
    const float* Wo = (const float*)d_in[8];
    const float* bo = (const float*)d_in[9];
    float* out = (float*)d_out;

    float *Qp, *Kp, *Vp, *Cp;
    cudaGetSymbolAddress((void**)&Qp, g_Q);
    cudaGetSymbolAddress((void**)&Kp, g_K);
    cudaGetSymbolAddress((void**)&Vp, g_V);
    cudaGetSymbolAddress((void**)&Cp, g_C);

    cudaFuncSetAttribute(gqa_flash_kernel,
                         cudaFuncAttributeMaxDynamicSharedMemorySize, ATT_SMEM);

    dim3 blk(256);
    // Projections
    sgemm_bias_kernel<<<dim3(DM / 128, MROWS / 128), blk>>>(x, Wq, bq, Qp, MROWS, DM, DM);
    sgemm_bias_kernel<<<dim3(KVW / 128, MROWS / 128), blk>>>(x, Wk, bk, Kp, MROWS, KVW, DM);
    sgemm_bias_kernel<<<dim3(KVW / 128, MROWS / 128), blk>>>(x, Wv, bv, Vp, MROWS, KVW, DM);
    // Attention
    gqa_flash_kernel<<<dim3(S_LEN / 64, NH, B_SZ), blk, ATT_SMEM>>>(Qp, Kp, Vp, Cp);
    // Output projection
    sgemm_bias_kernel<<<dim3(DM / 128, MROWS / 128), blk>>>(Cp, Wo, bo, out, MROWS, DM, DM);
}

// round 5
// speedup vs baseline: 1.6524x; 1.6524x over previous
#include <cuda_runtime.h>
#include <cuda_bf16.h>
#include <cstdint>
#include <math.h>

#define B_SZ   2
#define S_LEN  2048
#define DM     2048
#define NH     32
#define NKV    8
#define DK     64
#define KVW    (NKV * DK)      // 512
#define MROWS  (B_SZ * S_LEN)  // 4096

// ---------------- scratch (device globals; no allocation allowed) ----------
__device__ float g_Q[MROWS * DM];
__device__ float g_K[MROWS * KVW];
__device__ float g_V[MROWS * KVW];
__device__ float g_C[MROWS * DM];

__device__ __nv_bfloat16 g_xh[MROWS * DM], g_xl[MROWS * DM];
__device__ __nv_bfloat16 g_Ch[MROWS * DM], g_Cl[MROWS * DM];
__device__ __nv_bfloat16 g_Wqh[DM * DM],  g_Wql[DM * DM];    // stored [N][K]
__device__ __nv_bfloat16 g_Wkh[KVW * DM], g_Wkl[KVW * DM];
__device__ __nv_bfloat16 g_Wvh[KVW * DM], g_Wvl[KVW * DM];
__device__ __nv_bfloat16 g_Woh[DM * DM],  g_Wol[DM * DM];

// ---------------------------------------------------------------------------
// helpers
// ---------------------------------------------------------------------------
__device__ __forceinline__ void cp16(void* s, const void* g) {
    unsigned sa = (unsigned)__cvta_generic_to_shared(s);
    asm volatile("cp.async.cg.shared.global [%0], [%1], 16;\n" :: "r"(sa), "l"(g));
}

__device__ __forceinline__ void mma16816(float* c, const unsigned int* a,
                                         const unsigned int* b) {
    asm volatile(
        "mma.sync.aligned.m16n8k16.row.col.f32.bf16.bf16.f32 "
        "{%0,%1,%2,%3}, {%4,%5,%6,%7}, {%8,%9}, {%0,%1,%2,%3};\n"
        : "+f"(c[0]), "+f"(c[1]), "+f"(c[2]), "+f"(c[3])
        : "r"(a[0]), "r"(a[1]), "r"(a[2]), "r"(a[3]), "r"(b[0]), "r"(b[1]));
}

// ---------------------------------------------------------------------------
// split fp32 -> bf16 hi/lo (row-major, same layout)
// ---------------------------------------------------------------------------
__global__ void split_kernel(const float* __restrict__ s,
                             __nv_bfloat16* __restrict__ h,
                             __nv_bfloat16* __restrict__ lo, int n)
{
    int i = (blockIdx.x * blockDim.x + threadIdx.x) * 4;
    if (i >= n) return;
    float4 v = *(const float4*)(s + i);
    __nv_bfloat16 a0 = __float2bfloat16(v.x);
    __nv_bfloat16 a1 = __float2bfloat16(v.y);
    __nv_bfloat16 a2 = __float2bfloat16(v.z);
    __nv_bfloat16 a3 = __float2bfloat16(v.w);
    __nv_bfloat162 t;
    t.x = a0; t.y = a1; *(__nv_bfloat162*)(h + i) = t;
    t.x = a2; t.y = a3; *(__nv_bfloat162*)(h + i + 2) = t;
    t.x = __float2bfloat16(v.x - __bfloat162float(a0));
    t.y = __float2bfloat16(v.y - __bfloat162float(a1));
    *(__nv_bfloat162*)(lo + i) = t;
    t.x = __float2bfloat16(v.z - __bfloat162float(a2));
    t.y = __float2bfloat16(v.w - __bfloat162float(a3));
    *(__nv_bfloat162*)(lo + i + 2) = t;
}

// ---------------------------------------------------------------------------
// transpose + split: W [K][N] fp32 -> Th, Tl [N][K] bf16
// ---------------------------------------------------------------------------
__global__ void transpose_split(const float* __restrict__ W,
                                __nv_bfloat16* __restrict__ Th,
                                __nv_bfloat16* __restrict__ Tl, int K, int N)
{
    __shared__ float t[32][33];
    int bx = blockIdx.x * 32;   // n
    int by = blockIdx.y * 32;   // k
    int tx = threadIdx.x, ty = threadIdx.y;
#pragma unroll
    for (int i = 0; i < 32; i += 8)
        t[ty + i][tx] = W[(size_t)(by + ty + i) * N + bx + tx];
    __syncthreads();
#pragma unroll
    for (int i = 0; i < 32; i += 8) {
        float v = t[tx][ty + i];
        size_t o = (size_t)(bx + ty + i) * K + by + tx;
        __nv_bfloat16 h = __float2bfloat16(v);
        Th[o] = h;
        Tl[o] = __float2bfloat16(v - __bfloat162float(h));
    }
}

// ---------------------------------------------------------------------------
// bf16x3 tensor-core GEMM: C[M,N] = (Ah+Al)[M,K] @ (Bh+Bl)^T[N,K] + bias
// 128x128x32 tiles, 8 warps (2x4), warp tile 64x32, m16n8k16, 2-stage cp.async
// smem per stage: 4 tiles of 128x40 bf16 (pad 8) = 40960B; 2 stages = 81920B
// ---------------------------------------------------------------------------
#define GEMM_SMEM 81920

__global__ __launch_bounds__(256) void gemm_bf16x3(
    const __nv_bfloat16* __restrict__ Ah, const __nv_bfloat16* __restrict__ Al,
    const __nv_bfloat16* __restrict__ Bh, const __nv_bfloat16* __restrict__ Bl,
    const float* __restrict__ bias, float* __restrict__ C,
    int M, int N, int K)
{
    extern __shared__ __nv_bfloat16 sm[];
    const int tid = threadIdx.x;
    const int bm = blockIdx.y * 128;
    const int bn = blockIdx.x * 128;
    const int T = K >> 5;

    auto load_stage = [&](int s, int k0) {
        __nv_bfloat16* base = sm + s * 20480;
#pragma unroll
        for (int t = 0; t < 2; t++) {
            int c = tid + t * 256;          // 0..511
            int row = c >> 2;               // 0..127
            int seg = (c & 3) << 3;         // 0,8,16,24 (bf16 elems)
            size_t ga = (size_t)(bm + row) * K + k0 + seg;
            size_t gb = (size_t)(bn + row) * K + k0 + seg;
            int so = row * 40 + seg;
            cp16(base + so,          Ah + ga);
            cp16(base + 5120 + so,   Al + ga);
            cp16(base + 10240 + so,  Bh + gb);
            cp16(base + 15360 + so,  Bl + gb);
        }
    };

    const int w = tid >> 5, l = tid & 31;
    const int wm = (w >> 2) * 64;   // warp row offset (0/64)
    const int wn = (w & 3) * 32;    // warp col offset (0..96)
    const int qr = l >> 2;          // 0..7
    const int qc = (l & 3) * 2;     // 0,2,4,6

    float acc[4][4][4];
#pragma unroll
    for (int mi = 0; mi < 4; mi++)
#pragma unroll
        for (int ni = 0; ni < 4; ni++)
#pragma unroll
            for (int r = 0; r < 4; r++) acc[mi][ni][r] = 0.f;

    load_stage(0, 0);  asm volatile("cp.async.commit_group;\n");
    load_stage(1, 32); asm volatile("cp.async.commit_group;\n");

    for (int i = 0; i < T; i++) {
        if (i + 1 < T) asm volatile("cp.async.wait_group 1;\n" ::: "memory");
        else           asm volatile("cp.async.wait_group 0;\n" ::: "memory");
        __syncthreads();

        const __nv_bfloat16* Ahs = sm + (i & 1) * 20480;
        const __nv_bfloat16* Als = Ahs + 5120;
        const __nv_bfloat16* Bhs = Ahs + 10240;
        const __nv_bfloat16* Bls = Ahs + 15360;

#pragma unroll
        for (int ks = 0; ks < 32; ks += 16) {
            unsigned int ah[4][4], al[4][4];
#pragma unroll
            for (int mi = 0; mi < 4; mi++) {
                const __nv_bfloat16* p = Ahs + (wm + mi * 16 + qr) * 40 + ks + qc;
                ah[mi][0] = *(const unsigned int*)p;
                ah[mi][1] = *(const unsigned int*)(p + 320);
                ah[mi][2] = *(const unsigned int*)(p + 8);
                ah[mi][3] = *(const unsigned int*)(p + 328);
                const __nv_bfloat16* q = Als + (wm + mi * 16 + qr) * 40 + ks + qc;
                al[mi][0] = *(const unsigned int*)q;
                al[mi][1] = *(const unsigned int*)(q + 320);
                al[mi][2] = *(const unsigned int*)(q + 8);
                al[mi][3] = *(const unsigned int*)(q + 328);
            }
#pragma unroll
            for (int ni = 0; ni < 4; ni++) {
                const __nv_bfloat16* pb = Bhs + (wn + ni * 8 + qr) * 40 + ks + qc;
                unsigned int bh[2];
                bh[0] = *(const unsigned int*)pb;
                bh[1] = *(const unsigned int*)(pb + 8);
#pragma unroll
                for (int mi = 0; mi < 4; mi++) mma16816(acc[mi][ni], ah[mi], bh);
#pragma unroll
                for (int mi = 0; mi < 4; mi++) mma16816(acc[mi][ni], al[mi], bh);
                const __nv_bfloat16* pl = Bls + (wn + ni * 8 + qr) * 40 + ks + qc;
                unsigned int bl[2];
                bl[0] = *(const unsigned int*)pl;
                bl[1] = *(const unsigned int*)(pl + 8);
#pragma unroll
                for (int mi = 0; mi < 4; mi++) mma16816(acc[mi][ni], ah[mi], bl);
            }
        }
        __syncthreads();
        if (i + 2 < T) {
            load_stage(i & 1, (i + 2) * 32);
            asm volatile("cp.async.commit_group;\n");
        }
    }

    // epilogue: bias + store
#pragma unroll
    for (int mi = 0; mi < 4; mi++) {
#pragma unroll
        for (int ni = 0; ni < 4; ni++) {
            int r  = bm + wm + mi * 16 + qr;
            int cc = bn + wn + ni * 8 + qc;
            float b0 = bias[cc], b1 = bias[cc + 1];
            float2 v0, v1;
            v0.x = acc[mi][ni][0] + b0; v0.y = acc[mi][ni][1] + b1;
            v1.x = acc[mi][ni][2] + b0; v1.y = acc[mi][ni][3] + b1;
            *(float2*)(C + (size_t)r * N + cc)       = v0;
            *(float2*)(C + (size_t)(r + 8) * N + cc) = v1;
        }
    }
}

// ---------------------------------------------------------------------------
// Flash-attention (causal, GQA) — fp32, unchanged from R3
// ---------------------------------------------------------------------------
#define PITCH 68
#define ATT_SMEM (4 * 64 * PITCH * 4)

__global__ __launch_bounds__(256) void gqa_flash_kernel(
    const float* __restrict__ Q, const float* __restrict__ Kg,
    const float* __restrict__ Vg, float* __restrict__ Og)
{
    extern __shared__ float smf[];
    float* Qt = smf;
    float* Kt = Qt + 64 * PITCH;
    float* Vs = Kt + 64 * PITCH;
    float* Pt = Vs + 64 * PITCH;

    const int tid = threadIdx.x;
    const int tx = tid & 15;
    const int ty = tid >> 4;
    const int mtile = blockIdx.x;
    const int h = blockIdx.y;
    const int b = blockIdx.z;
    const int kvh = h >> 2;
    const int m0 = mtile * 64;

    const float* Qbase = Q + ((size_t)b * S_LEN + m0) * DM + h * DK;
    const float* Kbase = Kg + (size_t)b * S_LEN * KVW + kvh * DK;
    const float* Vbase = Vg + (size_t)b * S_LEN * KVW + kvh * DK;

#pragma unroll
    for (int t = 0; t < 4; t++) {
        int idx = tid + t * 256;
        int q = idx >> 4;
        int c = (idx & 15) * 4;
        float4 v = *(const float4*)(Qbase + (size_t)q * DM + c);
        Qt[(c + 0) * PITCH + q] = v.x;
        Qt[(c + 1) * PITCH + q] = v.y;
        Qt[(c + 2) * PITCH + q] = v.z;
        Qt[(c + 3) * PITCH + q] = v.w;
    }

    float m_i[4], l_i[4], acc[4][4];
#pragma unroll
    for (int i = 0; i < 4; i++) {
        m_i[i] = -INFINITY;
        l_i[i] = 0.f;
#pragma unroll
        for (int j = 0; j < 4; j++) acc[i][j] = 0.f;
    }

    for (int jt = 0; jt <= mtile; jt++) {
        __syncthreads();
        const int k0 = jt * 64;
#pragma unroll
        for (int t = 0; t < 4; t++) {
            int idx = tid + t * 256;
            int r = idx >> 4;
            int c = (idx & 15) * 4;
            float4 kv = *(const float4*)(Kbase + (size_t)(k0 + r) * KVW + c);
            Kt[(c + 0) * PITCH + r] = kv.x;
            Kt[(c + 1) * PITCH + r] = kv.y;
            Kt[(c + 2) * PITCH + r] = kv.z;
            Kt[(c + 3) * PITCH + r] = kv.w;
            *(float4*)&Vs[r * PITCH + c] =
                *(const float4*)(Vbase + (size_t)(k0 + r) * KVW + c);
        }
        __syncthreads();

        float s[4][4];
#pragma unroll
        for (int i = 0; i < 4; i++)
#pragma unroll
            for (int j = 0; j < 4; j++) s[i][j] = 0.f;

#pragma unroll 4
        for (int d = 0; d < 64; d++) {
            float4 qv = *(const float4*)&Qt[d * PITCH + ty * 4];
            float4 kv = *(const float4*)&Kt[d * PITCH + tx * 4];
            float qa[4] = {qv.x, qv.y, qv.z, qv.w};
            float ka[4] = {kv.x, kv.y, kv.z, kv.w};
#pragma unroll
            for (int i = 0; i < 4; i++)
#pragma unroll
                for (int j = 0; j < 4; j++)
                    s[i][j] = fmaf(qa[i], ka[j], s[i][j]);
        }

        const float rsc = 0.125f;
        if (jt == mtile) {
#pragma unroll
            for (int i = 0; i < 4; i++)
#pragma unroll
                for (int j = 0; j < 4; j++)
                    s[i][j] = (tx * 4 + j > ty * 4 + i) ? -INFINITY : s[i][j] * rsc;
        } else {
#pragma unroll
            for (int i = 0; i < 4; i++)
#pragma unroll
                for (int j = 0; j < 4; j++) s[i][j] *= rsc;
        }

#pragma unroll
        for (int i = 0; i < 4; i++) {
            float mx = fmaxf(fmaxf(s[i][0], s[i][1]), fmaxf(s[i][2], s[i][3]));
#pragma unroll
            for (int o = 8; o > 0; o >>= 1)
                mx = fmaxf(mx, __shfl_xor_sync(0xffffffffu, mx, o));
            float mnew = fmaxf(m_i[i], mx);
            float corr = __expf(m_i[i] - mnew);
            float ls = 0.f;
#pragma unroll
            for (int j = 0; j < 4; j++) {
                float p = __expf(s[i][j] - mnew);
                s[i][j] = p;
                ls += p;
            }
#pragma unroll
            for (int o = 8; o > 0; o >>= 1)
                ls += __shfl_xor_sync(0xffffffffu, ls, o);
            l_i[i] = l_i[i] * corr + ls;
            m_i[i] = mnew;
#pragma unroll
            for (int j = 0; j < 4; j++) acc[i][j] *= corr;
        }

#pragma unroll
        for (int i = 0; i < 4; i++)
#pragma unroll
            for (int j = 0; j < 4; j++)
                Pt[(tx * 4 + j) * PITCH + ty * 4 + i] = s[i][j];
        __syncthreads();

#pragma unroll 4
        for (int k = 0; k < 64; k++) {
            float4 pv = *(const float4*)&Pt[k * PITCH + ty * 4];
            float4 vv = *(const float4*)&Vs[k * PITCH + tx * 4];
            float pa[4] = {pv.x, pv.y, pv.z, pv.w};
            float va[4] = {vv.x, vv.y, vv.z, vv.w};
#pragma unroll
            for (int i = 0; i < 4; i++)
#pragma unroll
                for (int j = 0; j < 4; j++)
                    acc[i][j] = fmaf(pa[i], va[j], acc[i][j]);
        }
    }

    float* Ob = Og + ((size_t)b * S_LEN + m0) * DM + h * DK;
#pragma unroll
    for (int i = 0; i < 4; i++) {
        float inv = 1.f / l_i[i];
        float4 o;
        o.x = acc[i][0] * inv;
        o.y = acc[i][1] * inv;
        o.z = acc[i][2] * inv;
        o.w = acc[i][3] * inv;
        *(float4*)(Ob + (size_t)(ty * 4 + i) * DM + tx * 4) = o;
    }
}

// ---------------------------------------------------------------------------
// Launch
// ---------------------------------------------------------------------------
extern "C" void kernel_launch(void* const* d_in, const int* in_sizes, int n_in,
                              void* d_out, int out_size)
{
    (void)in_sizes; (void)n_in; (void)out_size;
    const float* x  = (const float*)d_in[0];
    const float* Wq = (const float*)d_in[2];
    const float* bq = (const float*)d_in[3];
    const float* Wk = (const float*)d_in[4];
    const float* bk = (const float*)d_in[5];
    const float* Wv = (const float*)d_in[6];
    const float* bv = (const float*)d_in[7];
    const float* Wo = (const float*)d_in[8];
    const float* bo = (const float*)d_in[9];
    float* out = (float*)d_out;

    float *Qp, *Kp, *Vp, *Cp;
    cudaGetSymbolAddress((void**)&Qp, g_Q);
    cudaGetSymbolAddress((void**)&Kp, g_K);
    cudaGetSymbolAddress((void**)&Vp, g_V);
    cudaGetSymbolAddress((void**)&Cp, g_C);
    __nv_bfloat16 *xh, *xl, *Ch, *Cl, *Wqh, *Wql, *Wkh, *Wkl, *Wvh, *Wvl, *Woh, *Wol;
    cudaGetSymbolAddress((void**)&xh, g_xh);   cudaGetSymbolAddress((void**)&xl, g_xl);
    cudaGetSymbolAddress((void**)&Ch, g_Ch);   cudaGetSymbolAddress((void**)&Cl, g_Cl);
    cudaGetSymbolAddress((void**)&Wqh, g_Wqh); cudaGetSymbolAddress((void**)&Wql, g_Wql);
    cudaGetSymbolAddress((void**)&Wkh, g_Wkh); cudaGetSymbolAddress((void**)&Wkl, g_Wkl);
    cudaGetSymbolAddress((void**)&Wvh, g_Wvh); cudaGetSymbolAddress((void**)&Wvl, g_Wvl);
    cudaGetSymbolAddress((void**)&Woh, g_Woh); cudaGetSymbolAddress((void**)&Wol, g_Wol);

    cudaFuncSetAttribute(gqa_flash_kernel,
                         cudaFuncAttributeMaxDynamicSharedMemorySize, ATT_SMEM);
    cudaFuncSetAttribute(gemm_bf16x3,
                         cudaFuncAttributeMaxDynamicSharedMemorySize, GEMM_SMEM);

    const int NX = MROWS * DM;

    // prep: splits + weight transposes (memory-bound, ~tens of µs)
    split_kernel<<<NX / 4 / 256, 256>>>(x, xh, xl, NX);
    transpose_split<<<dim3(DM / 32,  DM / 32), dim3(32, 8)>>>(Wq, Wqh, Wql, DM, DM);
    transpose_split<<<dim3(KVW / 32, DM / 32), dim3(32, 8)>>>(Wk, Wkh, Wkl, DM, KVW);
    transpose_split<<<dim3(KVW / 32, DM / 32), dim3(32, 8)>>>(Wv, Wvh, Wvl, DM, KVW);
    transpose_split<<<dim3(DM / 32,  DM / 32), dim3(32, 8)>>>(Wo, Woh, Wol, DM, DM);

    // projections on tensor cores
    gemm_bf16x3<<<dim3(DM / 128,  MROWS / 128), 256, GEMM_SMEM>>>(
        xh, xl, Wqh, Wql, bq, Qp, MROWS, DM, DM);
    gemm_bf16x3<<<dim3(KVW / 128, MROWS / 128), 256, GEMM_SMEM>>>(
        xh, xl, Wkh, Wkl, bk, Kp, MROWS, KVW, DM);
    gemm_bf16x3<<<dim3(KVW / 128, MROWS / 128), 256, GEMM_SMEM>>>(
        xh, xl, Wvh, Wvl, bv, Vp, MROWS, KVW, DM);

    // attention
    gqa_flash_kernel<<<dim3(S_LEN / 64, NH, B_SZ), 256, ATT_SMEM>>>(Qp, Kp, Vp, Cp);

    // output projection
    split_kernel<<<NX / 4 / 256, 256>>>(Cp, Ch, Cl, NX);
    gemm_bf16x3<<<dim3(DM / 128, MROWS / 128), 256, GEMM_SMEM>>>(
        Ch, Cl, Woh, Wol, bo, out, MROWS, DM, DM);
}

// round 6
// speedup vs baseline: 2.6387x; 1.5969x over previous
#include <cuda_runtime.h>
#include <cuda_bf16.h>
#include <cstdint>
#include <math.h>

#define B_SZ   2
#define S_LEN  2048
#define DM     2048
#define NH     32
#define NKV    8
#define DK     64
#define KVW    (NKV * DK)      // 512
#define MROWS  (B_SZ * S_LEN)  // 4096

// ---------------- scratch (device globals; no allocation allowed) ----------
__device__ __nv_bfloat16 g_xh[MROWS * DM],  g_xl[MROWS * DM];
__device__ __nv_bfloat16 g_Qh[MROWS * DM],  g_Ql[MROWS * DM];
__device__ __nv_bfloat16 g_Kh[MROWS * KVW], g_Kl[MROWS * KVW];
__device__ __nv_bfloat16 g_Vth[B_SZ * KVW * S_LEN], g_Vtl[B_SZ * KVW * S_LEN]; // [b][dk][s]
__device__ __nv_bfloat16 g_Ch[MROWS * DM],  g_Cl[MROWS * DM];
__device__ __nv_bfloat16 g_Wqh[DM * DM],   g_Wql[DM * DM];    // stored [N][K]
__device__ __nv_bfloat16 g_Wkh[KVW * DM],  g_Wkl[KVW * DM];
__device__ __nv_bfloat16 g_Wvh[KVW * DM],  g_Wvl[KVW * DM];
__device__ __nv_bfloat16 g_Woh[DM * DM],   g_Wol[DM * DM];

// ---------------------------------------------------------------------------
// helpers
// ---------------------------------------------------------------------------
__device__ __forceinline__ void cp16(void* s, const void* g) {
    unsigned sa = (unsigned)__cvta_generic_to_shared(s);
    asm volatile("cp.async.cg.shared.global [%0], [%1], 16;\n" :: "r"(sa), "l"(g));
}
#define CP_COMMIT() asm volatile("cp.async.commit_group;\n")
#define CP_WAIT(n)  asm volatile("cp.async.wait_group %0;\n" :: "n"(n) : "memory")

__device__ __forceinline__ void mma16816(float* c, const unsigned* a, const unsigned* b) {
    asm volatile(
        "mma.sync.aligned.m16n8k16.row.col.f32.bf16.bf16.f32 "
        "{%0,%1,%2,%3}, {%4,%5,%6,%7}, {%8,%9}, {%0,%1,%2,%3};\n"
        : "+f"(c[0]), "+f"(c[1]), "+f"(c[2]), "+f"(c[3])
        : "r"(a[0]), "r"(a[1]), "r"(a[2]), "r"(a[3]), "r"(b[0]), "r"(b[1]));
}

// pack two fp32 into bf16x2 hi + residual lo
__device__ __forceinline__ void split2(float v0, float v1, unsigned& hi, unsigned& lo) {
    __nv_bfloat162 h = __floats2bfloat162_rn(v0, v1);
    __nv_bfloat162 l = __floats2bfloat162_rn(v0 - __bfloat162float(h.x),
                                             v1 - __bfloat162float(h.y));
    hi = *(unsigned*)&h;
    lo = *(unsigned*)&l;
}

// ---------------------------------------------------------------------------
// split fp32 -> bf16 hi/lo (row-major, same layout)
// ---------------------------------------------------------------------------
__global__ void split_kernel(const float* __restrict__ s,
                             __nv_bfloat16* __restrict__ h,
                             __nv_bfloat16* __restrict__ lo, int n)
{
    int i = (blockIdx.x * blockDim.x + threadIdx.x) * 4;
    if (i >= n) return;
    float4 v = *(const float4*)(s + i);
    unsigned h0, l0, h1, l1;
    split2(v.x, v.y, h0, l0);
    split2(v.z, v.w, h1, l1);
    *(unsigned*)(h + i)      = h0;
    *(unsigned*)(h + i + 2)  = h1;
    *(unsigned*)(lo + i)     = l0;
    *(unsigned*)(lo + i + 2) = l1;
}

// ---------------------------------------------------------------------------
// transpose + split: W [K][N] fp32 -> Th, Tl [N][K] bf16
// ---------------------------------------------------------------------------
__global__ void transpose_split(const float* __restrict__ W,
                                __nv_bfloat16* __restrict__ Th,
                                __nv_bfloat16* __restrict__ Tl, int K, int N)
{
    __shared__ float t[32][33];
    int bx = blockIdx.x * 32;   // n
    int by = blockIdx.y * 32;   // k
    int tx = threadIdx.x, ty = threadIdx.y;
#pragma unroll
    for (int i = 0; i < 32; i += 8)
        t[ty + i][tx] = W[(size_t)(by + ty + i) * N + bx + tx];
    __syncthreads();
#pragma unroll
    for (int i = 0; i < 32; i += 8) {
        float v = t[tx][ty + i];
        size_t o = (size_t)(bx + ty + i) * K + by + tx;
        __nv_bfloat16 h = __float2bfloat16(v);
        Th[o] = h;
        Tl[o] = __float2bfloat16(v - __bfloat162float(h));
    }
}

// ---------------------------------------------------------------------------
// bf16x3 tensor-core GEMM, 128x128x32 tiles, epilogue modes:
//   0: fp32 + bias -> Cf
//   1: bias, split bf16 hi/lo row-major -> Coh/Col
//   2: bias, split bf16 hi/lo TRANSPOSED per batch -> Coh/Col [b][n][s]
// ---------------------------------------------------------------------------
#define GEMM_SMEM 81920

__global__ __launch_bounds__(256) void gemm_bf16x3(
    const __nv_bfloat16* __restrict__ Ah, const __nv_bfloat16* __restrict__ Al,
    const __nv_bfloat16* __restrict__ Bh, const __nv_bfloat16* __restrict__ Bl,
    const float* __restrict__ bias, float* __restrict__ Cf,
    __nv_bfloat16* __restrict__ Coh, __nv_bfloat16* __restrict__ Col,
    int mode, int M, int N, int K)
{
    extern __shared__ __nv_bfloat16 sm[];
    const int tid = threadIdx.x;
    const int bm = blockIdx.y * 128;
    const int bn = blockIdx.x * 128;
    const int T = K >> 5;

    auto load_stage = [&](int s, int k0) {
        __nv_bfloat16* base = sm + s * 20480;
#pragma unroll
        for (int t = 0; t < 2; t++) {
            int c = tid + t * 256;
            int row = c >> 2;
            int seg = (c & 3) << 3;
            size_t ga = (size_t)(bm + row) * K + k0 + seg;
            size_t gb = (size_t)(bn + row) * K + k0 + seg;
            int so = row * 40 + seg;
            cp16(base + so,         Ah + ga);
            cp16(base + 5120 + so,  Al + ga);
            cp16(base + 10240 + so, Bh + gb);
            cp16(base + 15360 + so, Bl + gb);
        }
    };

    const int w = tid >> 5, l = tid & 31;
    const int wm = (w >> 2) * 64;
    const int wn = (w & 3) * 32;
    const int qr = l >> 2;
    const int qc = (l & 3) * 2;

    float acc[4][4][4];
#pragma unroll
    for (int mi = 0; mi < 4; mi++)
#pragma unroll
        for (int ni = 0; ni < 4; ni++)
#pragma unroll
            for (int r = 0; r < 4; r++) acc[mi][ni][r] = 0.f;

    load_stage(0, 0);  CP_COMMIT();
    load_stage(1, 32); CP_COMMIT();

    for (int i = 0; i < T; i++) {
        if (i + 1 < T) CP_WAIT(1);
        else           CP_WAIT(0);
        __syncthreads();

        const __nv_bfloat16* Ahs = sm + (i & 1) * 20480;
        const __nv_bfloat16* Als = Ahs + 5120;
        const __nv_bfloat16* Bhs = Ahs + 10240;
        const __nv_bfloat16* Bls = Ahs + 15360;

#pragma unroll
        for (int ks = 0; ks < 32; ks += 16) {
            unsigned ah[4][4], al[4][4];
#pragma unroll
            for (int mi = 0; mi < 4; mi++) {
                const __nv_bfloat16* p = Ahs + (wm + mi * 16 + qr) * 40 + ks + qc;
                ah[mi][0] = *(const unsigned*)p;
                ah[mi][1] = *(const unsigned*)(p + 320);
                ah[mi][2] = *(const unsigned*)(p + 8);
                ah[mi][3] = *(const unsigned*)(p + 328);
                const __nv_bfloat16* q = Als + (wm + mi * 16 + qr) * 40 + ks + qc;
                al[mi][0] = *(const unsigned*)q;
                al[mi][1] = *(const unsigned*)(q + 320);
                al[mi][2] = *(const unsigned*)(q + 8);
                al[mi][3] = *(const unsigned*)(q + 328);
            }
#pragma unroll
            for (int ni = 0; ni < 4; ni++) {
                const __nv_bfloat16* pb = Bhs + (wn + ni * 8 + qr) * 40 + ks + qc;
                unsigned bh[2], bl[2];
                bh[0] = *(const unsigned*)pb;
                bh[1] = *(const unsigned*)(pb + 8);
#pragma unroll
                for (int mi = 0; mi < 4; mi++) mma16816(acc[mi][ni], ah[mi], bh);
#pragma unroll
                for (int mi = 0; mi < 4; mi++) mma16816(acc[mi][ni], al[mi], bh);
                const __nv_bfloat16* pl = Bls + (wn + ni * 8 + qr) * 40 + ks + qc;
                bl[0] = *(const unsigned*)pl;
                bl[1] = *(const unsigned*)(pl + 8);
#pragma unroll
                for (int mi = 0; mi < 4; mi++) mma16816(acc[mi][ni], ah[mi], bl);
            }
        }
        __syncthreads();
        if (i + 2 < T) {
            load_stage(i & 1, (i + 2) * 32);
            CP_COMMIT();
        }
    }

#pragma unroll
    for (int mi = 0; mi < 4; mi++) {
#pragma unroll
        for (int ni = 0; ni < 4; ni++) {
            int r  = bm + wm + mi * 16 + qr;
            int cc = bn + wn + ni * 8 + qc;
            float b0 = bias[cc], b1 = bias[cc + 1];
            float v0 = acc[mi][ni][0] + b0, v1 = acc[mi][ni][1] + b1;
            float v2 = acc[mi][ni][2] + b0, v3 = acc[mi][ni][3] + b1;
            if (mode == 0) {
                float2 a = {v0, v1}, bb = {v2, v3};
                *(float2*)(Cf + (size_t)r * N + cc)       = a;
                *(float2*)(Cf + (size_t)(r + 8) * N + cc) = bb;
            } else if (mode == 1) {
                unsigned h0, l0, h1, l1;
                split2(v0, v1, h0, l0);
                split2(v2, v3, h1, l1);
                *(unsigned*)(Coh + (size_t)r * N + cc)       = h0;
                *(unsigned*)(Col + (size_t)r * N + cc)       = l0;
                *(unsigned*)(Coh + (size_t)(r + 8) * N + cc) = h1;
                *(unsigned*)(Col + (size_t)(r + 8) * N + cc) = l1;
            } else {
                // transposed: out[b][n][s], s = r % S_LEN
                int bb2 = r >> 11;
                int sl  = r & (S_LEN - 1);
                size_t base = ((size_t)bb2 * KVW + cc) * S_LEN;
                __nv_bfloat16 h, lo2;
                h = __float2bfloat16(v0); lo2 = __float2bfloat16(v0 - __bfloat162float(h));
                Coh[base + sl] = h; Col[base + sl] = lo2;
                h = __float2bfloat16(v1); lo2 = __float2bfloat16(v1 - __bfloat162float(h));
                Coh[base + S_LEN + sl] = h; Col[base + S_LEN + sl] = lo2;
                h = __float2bfloat16(v2); lo2 = __float2bfloat16(v2 - __bfloat162float(h));
                Coh[base + sl + 8] = h; Col[base + sl + 8] = lo2;
                h = __float2bfloat16(v3); lo2 = __float2bfloat16(v3 - __bfloat162float(h));
                Coh[base + S_LEN + sl + 8] = h; Col[base + S_LEN + sl + 8] = lo2;
            }
        }
    }
}

// ---------------------------------------------------------------------------
// Tensor-core flash attention (causal, GQA), bf16x3 split precision.
// Block: 128 q rows, 8 warps x 16 rows. KV tiles of 64, cp.async double-buffer.
// smem bf16: Qh[128x72] Ql[128x72] | 2 stages of {Kh,Kl,Vth,Vtl}[64x72]
// ---------------------------------------------------------------------------
#define FL_SMEM ((18432 + 2 * 18432) * 2)   // 110592 bytes

__global__ __launch_bounds__(256) void gqa_flash_mma(
    const __nv_bfloat16* __restrict__ Qh_g, const __nv_bfloat16* __restrict__ Ql_g,
    const __nv_bfloat16* __restrict__ Kh_g, const __nv_bfloat16* __restrict__ Kl_g,
    const __nv_bfloat16* __restrict__ Vth_g, const __nv_bfloat16* __restrict__ Vtl_g,
    __nv_bfloat16* __restrict__ Ch_g, __nv_bfloat16* __restrict__ Cl_g)
{
    extern __shared__ __nv_bfloat16 sb[];
    const int tid = threadIdx.x;
    const int w = tid >> 5, l = tid & 31;
    const int qr = l >> 2, qc = (l & 3) * 2;
    const int mtile = blockIdx.x, h = blockIdx.y, b = blockIdx.z;
    const int kvh = h >> 2;
    const int m0 = mtile * 128;
    const int kvTiles = 2 * mtile + 2;
    const int lastTile = 2 * mtile + (w >> 2);   // per-warp causal skip

    // ---- Q loads (with stage0 in group 0) ----
    const __nv_bfloat16* Qph = Qh_g + ((size_t)(b * S_LEN + m0)) * DM + h * 64;
    const __nv_bfloat16* Qpl = Ql_g + ((size_t)(b * S_LEN + m0)) * DM + h * 64;
#pragma unroll
    for (int t = 0; t < 4; t++) {
        int idx = tid + t * 256;           // 0..1023
        int row = idx >> 3, seg = (idx & 7) * 8;
        cp16(sb + row * 72 + seg,        Qph + (size_t)row * DM + seg);
        cp16(sb + 9216 + row * 72 + seg, Qpl + (size_t)row * DM + seg);
    }

    auto load_kv = [&](int sidx, int jt) {
        __nv_bfloat16* st = sb + 18432 + sidx * 18432;
        const int k0 = jt * 64;
        const __nv_bfloat16* Kgh = Kh_g + ((size_t)(b * S_LEN + k0)) * KVW + kvh * 64;
        const __nv_bfloat16* Kgl = Kl_g + ((size_t)(b * S_LEN + k0)) * KVW + kvh * 64;
        const __nv_bfloat16* Vgh = Vth_g + ((size_t)b * KVW + kvh * 64) * S_LEN + k0;
        const __nv_bfloat16* Vgl = Vtl_g + ((size_t)b * KVW + kvh * 64) * S_LEN + k0;
#pragma unroll
        for (int t = 0; t < 2; t++) {
            int idx = tid + t * 256;       // 0..511
            int row = idx >> 3, seg = (idx & 7) * 8;
            cp16(st + row * 72 + seg,         Kgh + (size_t)row * KVW + seg);
            cp16(st + 4608 + row * 72 + seg,  Kgl + (size_t)row * KVW + seg);
            cp16(st + 9216 + row * 72 + seg,  Vgh + (size_t)row * S_LEN + seg);
            cp16(st + 13824 + row * 72 + seg, Vgl + (size_t)row * S_LEN + seg);
        }
    };

    load_kv(0, 0); CP_COMMIT();
    load_kv(1, 1); CP_COMMIT();

    CP_WAIT(1);
    __syncthreads();

    // ---- build Q fragments (held in registers for whole kernel) ----
    unsigned aqh[4][4], aql[4][4];
#pragma unroll
    for (int j = 0; j < 4; j++) {
        const __nv_bfloat16* p = sb + (w * 16 + qr) * 72 + j * 16 + qc;
        aqh[j][0] = *(const unsigned*)p;
        aqh[j][1] = *(const unsigned*)(p + 8 * 72);
        aqh[j][2] = *(const unsigned*)(p + 8);
        aqh[j][3] = *(const unsigned*)(p + 8 * 72 + 8);
        const __nv_bfloat16* q = p + 9216;
        aql[j][0] = *(const unsigned*)q;
        aql[j][1] = *(const unsigned*)(q + 8 * 72);
        aql[j][2] = *(const unsigned*)(q + 8);
        aql[j][3] = *(const unsigned*)(q + 8 * 72 + 8);
    }

    float o[8][4];
#pragma unroll
    for (int n = 0; n < 8; n++)
#pragma unroll
        for (int r = 0; r < 4; r++) o[n][r] = 0.f;
    float mrow0 = -INFINITY, mrow1 = -INFINITY, lrow0 = 0.f, lrow1 = 0.f;

    const int r0 = m0 + w * 16 + qr;
    const int r1 = r0 + 8;

    for (int jt = 0; jt < kvTiles; jt++) {
        if (jt > 0) {
            if (jt + 1 < kvTiles) CP_WAIT(1);
            else                  CP_WAIT(0);
            __syncthreads();
        }
        const __nv_bfloat16* st = sb + 18432 + (jt & 1) * 18432;

        if (jt <= lastTile) {
            const int k0 = jt * 64;
            float s[8][4];
#pragma unroll
            for (int n = 0; n < 8; n++)
#pragma unroll
                for (int r = 0; r < 4; r++) s[n][r] = 0.f;

            // S = Q K^T (bf16x3)
#pragma unroll
            for (int j = 0; j < 4; j++) {
#pragma unroll
                for (int n = 0; n < 8; n++) {
                    const __nv_bfloat16* pb = st + (n * 8 + qr) * 72 + j * 16 + qc;
                    unsigned bh[2], bl[2];
                    bh[0] = *(const unsigned*)pb;
                    bh[1] = *(const unsigned*)(pb + 8);
                    bl[0] = *(const unsigned*)(pb + 4608);
                    bl[1] = *(const unsigned*)(pb + 4608 + 8);
                    mma16816(s[n], aqh[j], bh);
                    mma16816(s[n], aql[j], bh);
                    mma16816(s[n], aqh[j], bl);
                }
            }

            // scale + causal mask
            const float rs = 0.125f;
            if (k0 + 63 > m0 + w * 16) {
#pragma unroll
                for (int n = 0; n < 8; n++) {
                    int c0 = k0 + n * 8 + qc;
                    s[n][0] = (c0     > r0) ? -1e30f : s[n][0] * rs;
                    s[n][1] = (c0 + 1 > r0) ? -1e30f : s[n][1] * rs;
                    s[n][2] = (c0     > r1) ? -1e30f : s[n][2] * rs;
                    s[n][3] = (c0 + 1 > r1) ? -1e30f : s[n][3] * rs;
                }
            } else {
#pragma unroll
                for (int n = 0; n < 8; n++)
#pragma unroll
                    for (int r = 0; r < 4; r++) s[n][r] *= rs;
            }

            // online softmax (rows r0, r1); row spread over 4 lanes of the quad
            float mx0 = -1e30f, mx1 = -1e30f;
#pragma unroll
            for (int n = 0; n < 8; n++) {
                mx0 = fmaxf(mx0, fmaxf(s[n][0], s[n][1]));
                mx1 = fmaxf(mx1, fmaxf(s[n][2], s[n][3]));
            }
            mx0 = fmaxf(mx0, __shfl_xor_sync(0xffffffffu, mx0, 1));
            mx0 = fmaxf(mx0, __shfl_xor_sync(0xffffffffu, mx0, 2));
            mx1 = fmaxf(mx1, __shfl_xor_sync(0xffffffffu, mx1, 1));
            mx1 = fmaxf(mx1, __shfl_xor_sync(0xffffffffu, mx1, 2));
            float mn0 = fmaxf(mrow0, mx0), mn1 = fmaxf(mrow1, mx1);
            float cr0 = __expf(mrow0 - mn0), cr1 = __expf(mrow1 - mn1);
            float sum0 = 0.f, sum1 = 0.f;
#pragma unroll
            for (int n = 0; n < 8; n++) {
                s[n][0] = __expf(s[n][0] - mn0);
                s[n][1] = __expf(s[n][1] - mn0);
                s[n][2] = __expf(s[n][2] - mn1);
                s[n][3] = __expf(s[n][3] - mn1);
                sum0 += s[n][0] + s[n][1];
                sum1 += s[n][2] + s[n][3];
            }
            sum0 += __shfl_xor_sync(0xffffffffu, sum0, 1);
            sum0 += __shfl_xor_sync(0xffffffffu, sum0, 2);
            sum1 += __shfl_xor_sync(0xffffffffu, sum1, 1);
            sum1 += __shfl_xor_sync(0xffffffffu, sum1, 2);
            lrow0 = lrow0 * cr0 + sum0;
            lrow1 = lrow1 * cr1 + sum1;
            mrow0 = mn0; mrow1 = mn1;
#pragma unroll
            for (int n = 0; n < 8; n++) {
                o[n][0] *= cr0; o[n][1] *= cr0;
                o[n][2] *= cr1; o[n][3] *= cr1;
            }

            // P fragments in registers (C-frag of ntiles 2j,2j+1 == A-frag of ktile j)
            unsigned pah[4][4], pal[4][4];
#pragma unroll
            for (int j = 0; j < 4; j++) {
                split2(s[2 * j][0],     s[2 * j][1],     pah[j][0], pal[j][0]);
                split2(s[2 * j][2],     s[2 * j][3],     pah[j][1], pal[j][1]);
                split2(s[2 * j + 1][0], s[2 * j + 1][1], pah[j][2], pal[j][2]);
                split2(s[2 * j + 1][2], s[2 * j + 1][3], pah[j][3], pal[j][3]);
            }

            // O += P V (bf16x3); Vt smem is [dk][kseq]
#pragma unroll
            for (int j = 0; j < 4; j++) {
#pragma unroll
                for (int n = 0; n < 8; n++) {
                    const __nv_bfloat16* pv = st + 9216 + (n * 8 + qr) * 72 + j * 16 + qc;
                    unsigned bh[2], bl[2];
                    bh[0] = *(const unsigned*)pv;
                    bh[1] = *(const unsigned*)(pv + 8);
                    bl[0] = *(const unsigned*)(pv + 4608);
                    bl[1] = *(const unsigned*)(pv + 4608 + 8);
                    mma16816(o[n], pah[j], bh);
                    mma16816(o[n], pal[j], bh);
                    mma16816(o[n], pah[j], bl);
                }
            }
        }

        __syncthreads();
        if (jt + 2 < kvTiles) {
            load_kv(jt & 1, jt + 2);
            CP_COMMIT();
        }
    }

    // ---- epilogue: normalize, split, store bf16 hi/lo context ----
    float inv0 = 1.f / lrow0, inv1 = 1.f / lrow1;
    size_t base0 = ((size_t)(b * S_LEN) + r0) * DM + h * 64;
    size_t base1 = ((size_t)(b * S_LEN) + r1) * DM + h * 64;
#pragma unroll
    for (int n = 0; n < 8; n++) {
        unsigned hh, ll;
        split2(o[n][0] * inv0, o[n][1] * inv0, hh, ll);
        *(unsigned*)(Ch_g + base0 + n * 8 + qc) = hh;
        *(unsigned*)(Cl_g + base0 + n * 8 + qc) = ll;
        split2(o[n][2] * inv1, o[n][3] * inv1, hh, ll);
        *(unsigned*)(Ch_g + base1 + n * 8 + qc) = hh;
        *(unsigned*)(Cl_g + base1 + n * 8 + qc) = ll;
    }
}

// ---------------------------------------------------------------------------
// Launch
// ---------------------------------------------------------------------------
extern "C" void kernel_launch(void* const* d_in, const int* in_sizes, int n_in,
                              void* d_out, int out_size)
{
    (void)in_sizes; (void)n_in; (void)out_size;
    const float* x  = (const float*)d_in[0];
    const float* Wq = (const float*)d_in[2];
    const float* bq = (const float*)d_in[3];
    const float* Wk = (const float*)d_in[4];
    const float* bk = (const float*)d_in[5];
    const float* Wv = (const float*)d_in[6];
    const float* bv = (const float*)d_in[7];
    const float* Wo = (const float*)d_in[8];
    const float* bo = (const float*)d_in[9];
    float* out = (float*)d_out;

    __nv_bfloat16 *xh, *xl, *Qh, *Ql, *Kh, *Kl, *Vth, *Vtl, *Ch, *Cl;
    __nv_bfloat16 *Wqh, *Wql, *Wkh, *Wkl, *Wvh, *Wvl, *Woh, *Wol;
    cudaGetSymbolAddress((void**)&xh, g_xh);   cudaGetSymbolAddress((void**)&xl, g_xl);
    cudaGetSymbolAddress((void**)&Qh, g_Qh);   cudaGetSymbolAddress((void**)&Ql, g_Ql);
    cudaGetSymbolAddress((void**)&Kh, g_Kh);   cudaGetSymbolAddress((void**)&Kl, g_Kl);
    cudaGetSymbolAddress((void**)&Vth, g_Vth); cudaGetSymbolAddress((void**)&Vtl, g_Vtl);
    cudaGetSymbolAddress((void**)&Ch, g_Ch);   cudaGetSymbolAddress((void**)&Cl, g_Cl);
    cudaGetSymbolAddress((void**)&Wqh, g_Wqh); cudaGetSymbolAddress((void**)&Wql, g_Wql);
    cudaGetSymbolAddress((void**)&Wkh, g_Wkh); cudaGetSymbolAddress((void**)&Wkl, g_Wkl);
    cudaGetSymbolAddress((void**)&Wvh, g_Wvh); cudaGetSymbolAddress((void**)&Wvl, g_Wvl);
    cudaGetSymbolAddress((void**)&Woh, g_Woh); cudaGetSymbolAddress((void**)&Wol, g_Wol);

    cudaFuncSetAttribute(gemm_bf16x3,
                         cudaFuncAttributeMaxDynamicSharedMemorySize, GEMM_SMEM);
    cudaFuncSetAttribute(gqa_flash_mma,
                         cudaFuncAttributeMaxDynamicSharedMemorySize, FL_SMEM);

    const int NX = MROWS * DM;

    // prep
    split_kernel<<<NX / 4 / 256, 256>>>(x, xh, xl, NX);
    transpose_split<<<dim3(DM / 32,  DM / 32), dim3(32, 8)>>>(Wq, Wqh, Wql, DM, DM);
    transpose_split<<<dim3(KVW / 32, DM / 32), dim3(32, 8)>>>(Wk, Wkh, Wkl, DM, KVW);
    transpose_split<<<dim3(KVW / 32, DM / 32), dim3(32, 8)>>>(Wv, Wvh, Wvl, DM, KVW);
    transpose_split<<<dim3(DM / 32,  DM / 32), dim3(32, 8)>>>(Wo, Woh, Wol, DM, DM);

    // projections (Q,K -> bf16 split; V -> transposed bf16 split)
    gemm_bf16x3<<<dim3(DM / 128,  MROWS / 128), 256, GEMM_SMEM>>>(
        xh, xl, Wqh, Wql, bq, nullptr, Qh, Ql, 1, MROWS, DM, DM);
    gemm_bf16x3<<<dim3(KVW / 128, MROWS / 128), 256, GEMM_SMEM>>>(
        xh, xl, Wkh, Wkl, bk, nullptr, Kh, Kl, 1, MROWS, KVW, DM);
    gemm_bf16x3<<<dim3(KVW / 128, MROWS / 128), 256, GEMM_SMEM>>>(
        xh, xl, Wvh, Wvl, bv, nullptr, Vth, Vtl, 2, MROWS, KVW, DM);

    // attention (tensor cores, writes context split directly)
    gqa_flash_mma<<<dim3(S_LEN / 128, NH, B_SZ), 256, FL_SMEM>>>(
        Qh, Ql, Kh, Kl, Vth, Vtl, Ch, Cl);

    // output projection (fp32 out)
    gemm_bf16x3<<<dim3(DM / 128, MROWS / 128), 256, GEMM_SMEM>>>(
        Ch, Cl, Woh, Wol, bo, out, nullptr, nullptr, 0, MROWS, DM, DM);
}

// round 7
// speedup vs baseline: 2.7171x; 1.0297x over previous
#include <cuda_runtime.h>
#include <cuda_bf16.h>
#include <cstdint>
#include <math.h>

#define B_SZ   2
#define S_LEN  2048
#define DM     2048
#define NH     32
#define NKV    8
#define DK     64
#define KVW    (NKV * DK)      // 512
#define MROWS  (B_SZ * S_LEN)  // 4096

// ---------------- scratch (device globals; no allocation allowed) ----------
__device__ __nv_bfloat16 g_xh[MROWS * DM],  g_xl[MROWS * DM];
__device__ __nv_bfloat16 g_Qh[MROWS * DM],  g_Ql[MROWS * DM];
__device__ __nv_bfloat16 g_Kh[MROWS * KVW], g_Kl[MROWS * KVW];
__device__ __nv_bfloat16 g_Vth[B_SZ * KVW * S_LEN], g_Vtl[B_SZ * KVW * S_LEN]; // [b][dk][s]
__device__ __nv_bfloat16 g_Ch[MROWS * DM],  g_Cl[MROWS * DM];
__device__ __nv_bfloat16 g_Wqh[DM * DM],   g_Wql[DM * DM];    // stored [N][K]
__device__ __nv_bfloat16 g_Wkh[KVW * DM],  g_Wkl[KVW * DM];
__device__ __nv_bfloat16 g_Wvh[KVW * DM],  g_Wvl[KVW * DM];
__device__ __nv_bfloat16 g_Woh[DM * DM],   g_Wol[DM * DM];

// ---------------------------------------------------------------------------
// helpers
// ---------------------------------------------------------------------------
__device__ __forceinline__ void cp16(void* s, const void* g) {
    unsigned sa = (unsigned)__cvta_generic_to_shared(s);
    asm volatile("cp.async.cg.shared.global [%0], [%1], 16;\n" :: "r"(sa), "l"(g));
}
#define CP_COMMIT() asm volatile("cp.async.commit_group;\n")
#define CP_WAIT(n)  asm volatile("cp.async.wait_group %0;\n" :: "n"(n) : "memory")

__device__ __forceinline__ void mma16816(float* c, const unsigned* a, const unsigned* b) {
    asm volatile(
        "mma.sync.aligned.m16n8k16.row.col.f32.bf16.bf16.f32 "
        "{%0,%1,%2,%3}, {%4,%5,%6,%7}, {%8,%9}, {%0,%1,%2,%3};\n"
        : "+f"(c[0]), "+f"(c[1]), "+f"(c[2]), "+f"(c[3])
        : "r"(a[0]), "r"(a[1]), "r"(a[2]), "r"(a[3]), "r"(b[0]), "r"(b[1]));
}

__device__ __forceinline__ void ldsm_x4(unsigned* r, const void* p) {
    unsigned a = (unsigned)__cvta_generic_to_shared(p);
    asm volatile("ldmatrix.sync.aligned.m8n8.x4.shared.b16 {%0,%1,%2,%3}, [%4];\n"
                 : "=r"(r[0]), "=r"(r[1]), "=r"(r[2]), "=r"(r[3]) : "r"(a));
}

// pack two fp32 into bf16x2 hi + residual lo
__device__ __forceinline__ void split2(float v0, float v1, unsigned& hi, unsigned& lo) {
    __nv_bfloat162 h = __floats2bfloat162_rn(v0, v1);
    __nv_bfloat162 l = __floats2bfloat162_rn(v0 - __bfloat162float(h.x),
                                             v1 - __bfloat162float(h.y));
    hi = *(unsigned*)&h;
    lo = *(unsigned*)&l;
}

// ---------------------------------------------------------------------------
// split fp32 -> bf16 hi/lo (row-major, same layout)
// ---------------------------------------------------------------------------
__global__ void split_kernel(const float* __restrict__ s,
                             __nv_bfloat16* __restrict__ h,
                             __nv_bfloat16* __restrict__ lo, int n)
{
    int i = (blockIdx.x * blockDim.x + threadIdx.x) * 4;
    if (i >= n) return;
    float4 v = *(const float4*)(s + i);
    unsigned h0, l0, h1, l1;
    split2(v.x, v.y, h0, l0);
    split2(v.z, v.w, h1, l1);
    *(unsigned*)(h + i)      = h0;
    *(unsigned*)(h + i + 2)  = h1;
    *(unsigned*)(lo + i)     = l0;
    *(unsigned*)(lo + i + 2) = l1;
}

// ---------------------------------------------------------------------------
// transpose + split: W [K][N] fp32 -> Th, Tl [N][K] bf16
// ---------------------------------------------------------------------------
__global__ void transpose_split(const float* __restrict__ W,
                                __nv_bfloat16* __restrict__ Th,
                                __nv_bfloat16* __restrict__ Tl, int K, int N)
{
    __shared__ float t[32][33];
    int bx = blockIdx.x * 32;   // n
    int by = blockIdx.y * 32;   // k
    int tx = threadIdx.x, ty = threadIdx.y;
#pragma unroll
    for (int i = 0; i < 32; i += 8)
        t[ty + i][tx] = W[(size_t)(by + ty + i) * N + bx + tx];
    __syncthreads();
#pragma unroll
    for (int i = 0; i < 32; i += 8) {
        float v = t[tx][ty + i];
        size_t o = (size_t)(bx + ty + i) * K + by + tx;
        __nv_bfloat16 h = __float2bfloat16(v);
        Th[o] = h;
        Tl[o] = __float2bfloat16(v - __bfloat162float(h));
    }
}

// ---------------------------------------------------------------------------
// bf16x3 tensor-core GEMM, 128x128x32 tiles, ldmatrix fragment feed.
// epilogue modes: 0 fp32+bias; 1 split bf16 row-major; 2 split bf16 transposed
// ---------------------------------------------------------------------------
#define GEMM_SMEM 81920

__global__ __launch_bounds__(256) void gemm_bf16x3(
    const __nv_bfloat16* __restrict__ Ah, const __nv_bfloat16* __restrict__ Al,
    const __nv_bfloat16* __restrict__ Bh, const __nv_bfloat16* __restrict__ Bl,
    const float* __restrict__ bias, float* __restrict__ Cf,
    __nv_bfloat16* __restrict__ Coh, __nv_bfloat16* __restrict__ Col,
    int mode, int M, int N, int K)
{
    extern __shared__ __nv_bfloat16 sm[];
    const int tid = threadIdx.x;
    const int bm = blockIdx.y * 128;
    const int bn = blockIdx.x * 128;
    const int T = K >> 5;

    auto load_stage = [&](int s, int k0) {
        __nv_bfloat16* base = sm + s * 20480;
#pragma unroll
        for (int t = 0; t < 2; t++) {
            int c = tid + t * 256;
            int row = c >> 2;
            int seg = (c & 3) << 3;
            size_t ga = (size_t)(bm + row) * K + k0 + seg;
            size_t gb = (size_t)(bn + row) * K + k0 + seg;
            int so = row * 40 + seg;
            cp16(base + so,         Ah + ga);
            cp16(base + 5120 + so,  Al + ga);
            cp16(base + 10240 + so, Bh + gb);
            cp16(base + 15360 + so, Bl + gb);
        }
    };

    const int w = tid >> 5, l = tid & 31;
    const int wm = (w >> 2) * 64;
    const int wn = (w & 3) * 32;
    const int qr = l >> 2;
    const int qc = (l & 3) * 2;
    // ldmatrix lane addressing
    const int arow = (l & 7) + ((l >> 3) & 1) * 8;   // A: row within m16
    const int acol = (l >> 4) * 8;                   // A: col offset (0/8)
    const int brow = (l & 7) + ((l >> 4) & 1) * 8;   // B: row within n16 (2 n-tiles)
    const int bcol = ((l >> 3) & 1) * 8;             // B: col offset (0/8)

    float acc[4][4][4];
#pragma unroll
    for (int mi = 0; mi < 4; mi++)
#pragma unroll
        for (int ni = 0; ni < 4; ni++)
#pragma unroll
            for (int r = 0; r < 4; r++) acc[mi][ni][r] = 0.f;

    load_stage(0, 0);  CP_COMMIT();
    load_stage(1, 32); CP_COMMIT();

    for (int i = 0; i < T; i++) {
        if (i + 1 < T) CP_WAIT(1);
        else           CP_WAIT(0);
        __syncthreads();

        const __nv_bfloat16* Ahs = sm + (i & 1) * 20480;
        const __nv_bfloat16* Als = Ahs + 5120;
        const __nv_bfloat16* Bhs = Ahs + 10240;
        const __nv_bfloat16* Bls = Ahs + 15360;

#pragma unroll
        for (int ks = 0; ks < 32; ks += 16) {
            unsigned ah[4][4], al[4][4];
#pragma unroll
            for (int mi = 0; mi < 4; mi++) {
                ldsm_x4(ah[mi], Ahs + (wm + mi * 16 + arow) * 40 + ks + acol);
                ldsm_x4(al[mi], Als + (wm + mi * 16 + arow) * 40 + ks + acol);
            }
#pragma unroll
            for (int p = 0; p < 2; p++) {
                unsigned bh[4], bl[4];
                ldsm_x4(bh, Bhs + (wn + p * 16 + brow) * 40 + ks + bcol);
                ldsm_x4(bl, Bls + (wn + p * 16 + brow) * 40 + ks + bcol);
#pragma unroll
                for (int mi = 0; mi < 4; mi++) {
                    mma16816(acc[mi][2 * p],     ah[mi], bh);
                    mma16816(acc[mi][2 * p],     al[mi], bh);
                    mma16816(acc[mi][2 * p],     ah[mi], bl);
                    mma16816(acc[mi][2 * p + 1], ah[mi], bh + 2);
                    mma16816(acc[mi][2 * p + 1], al[mi], bh + 2);
                    mma16816(acc[mi][2 * p + 1], ah[mi], bl + 2);
                }
            }
        }
        __syncthreads();
        if (i + 2 < T) {
            load_stage(i & 1, (i + 2) * 32);
            CP_COMMIT();
        }
    }

#pragma unroll
    for (int mi = 0; mi < 4; mi++) {
#pragma unroll
        for (int ni = 0; ni < 4; ni++) {
            int r  = bm + wm + mi * 16 + qr;
            int cc = bn + wn + ni * 8 + qc;
            float b0 = bias[cc], b1 = bias[cc + 1];
            float v0 = acc[mi][ni][0] + b0, v1 = acc[mi][ni][1] + b1;
            float v2 = acc[mi][ni][2] + b0, v3 = acc[mi][ni][3] + b1;
            if (mode == 0) {
                float2 a = {v0, v1}, bb = {v2, v3};
                *(float2*)(Cf + (size_t)r * N + cc)       = a;
                *(float2*)(Cf + (size_t)(r + 8) * N + cc) = bb;
            } else if (mode == 1) {
                unsigned h0, l0, h1, l1;
                split2(v0, v1, h0, l0);
                split2(v2, v3, h1, l1);
                *(unsigned*)(Coh + (size_t)r * N + cc)       = h0;
                *(unsigned*)(Col + (size_t)r * N + cc)       = l0;
                *(unsigned*)(Coh + (size_t)(r + 8) * N + cc) = h1;
                *(unsigned*)(Col + (size_t)(r + 8) * N + cc) = l1;
            } else {
                int bb2 = r >> 11;
                int sl  = r & (S_LEN - 1);
                size_t base = ((size_t)bb2 * KVW + cc) * S_LEN;
                __nv_bfloat16 h, lo2;
                h = __float2bfloat16(v0); lo2 = __float2bfloat16(v0 - __bfloat162float(h));
                Coh[base + sl] = h; Col[base + sl] = lo2;
                h = __float2bfloat16(v1); lo2 = __float2bfloat16(v1 - __bfloat162float(h));
                Coh[base + S_LEN + sl] = h; Col[base + S_LEN + sl] = lo2;
                h = __float2bfloat16(v2); lo2 = __float2bfloat16(v2 - __bfloat162float(h));
                Coh[base + sl + 8] = h; Col[base + sl + 8] = lo2;
                h = __float2bfloat16(v3); lo2 = __float2bfloat16(v3 - __bfloat162float(h));
                Coh[base + S_LEN + sl + 8] = h; Col[base + S_LEN + sl + 8] = lo2;
            }
        }
    }
}

// ---------------------------------------------------------------------------
// Tensor-core flash attention (causal, GQA), bf16x3, ldmatrix fragment feed.
// ---------------------------------------------------------------------------
#define FL_SMEM ((18432 + 2 * 18432) * 2)   // 110592 bytes

__global__ __launch_bounds__(256) void gqa_flash_mma(
    const __nv_bfloat16* __restrict__ Qh_g, const __nv_bfloat16* __restrict__ Ql_g,
    const __nv_bfloat16* __restrict__ Kh_g, const __nv_bfloat16* __restrict__ Kl_g,
    const __nv_bfloat16* __restrict__ Vth_g, const __nv_bfloat16* __restrict__ Vtl_g,
    __nv_bfloat16* __restrict__ Ch_g, __nv_bfloat16* __restrict__ Cl_g)
{
    extern __shared__ __nv_bfloat16 sb[];
    const int tid = threadIdx.x;
    const int w = tid >> 5, l = tid & 31;
    const int qr = l >> 2, qc = (l & 3) * 2;
    const int arow = (l & 7) + ((l >> 3) & 1) * 8;
    const int acol = (l >> 4) * 8;
    const int brow = (l & 7) + ((l >> 4) & 1) * 8;
    const int bcol = ((l >> 3) & 1) * 8;
    const int mtile = blockIdx.x, h = blockIdx.y, b = blockIdx.z;
    const int kvh = h >> 2;
    const int m0 = mtile * 128;
    const int kvTiles = 2 * mtile + 2;
    const int lastTile = 2 * mtile + (w >> 2);   // per-warp causal skip

    // ---- Q loads ----
    const __nv_bfloat16* Qph = Qh_g + ((size_t)(b * S_LEN + m0)) * DM + h * 64;
    const __nv_bfloat16* Qpl = Ql_g + ((size_t)(b * S_LEN + m0)) * DM + h * 64;
#pragma unroll
    for (int t = 0; t < 4; t++) {
        int idx = tid + t * 256;
        int row = idx >> 3, seg = (idx & 7) * 8;
        cp16(sb + row * 72 + seg,        Qph + (size_t)row * DM + seg);
        cp16(sb + 9216 + row * 72 + seg, Qpl + (size_t)row * DM + seg);
    }

    auto load_kv = [&](int sidx, int jt) {
        __nv_bfloat16* st = sb + 18432 + sidx * 18432;
        const int k0 = jt * 64;
        const __nv_bfloat16* Kgh = Kh_g + ((size_t)(b * S_LEN + k0)) * KVW + kvh * 64;
        const __nv_bfloat16* Kgl = Kl_g + ((size_t)(b * S_LEN + k0)) * KVW + kvh * 64;
        const __nv_bfloat16* Vgh = Vth_g + ((size_t)b * KVW + kvh * 64) * S_LEN + k0;
        const __nv_bfloat16* Vgl = Vtl_g + ((size_t)b * KVW + kvh * 64) * S_LEN + k0;
#pragma unroll
        for (int t = 0; t < 2; t++) {
            int idx = tid + t * 256;
            int row = idx >> 3, seg = (idx & 7) * 8;
            cp16(st + row * 72 + seg,         Kgh + (size_t)row * KVW + seg);
            cp16(st + 4608 + row * 72 + seg,  Kgl + (size_t)row * KVW + seg);
            cp16(st + 9216 + row * 72 + seg,  Vgh + (size_t)row * S_LEN + seg);
            cp16(st + 13824 + row * 72 + seg, Vgl + (size_t)row * S_LEN + seg);
        }
    };

    load_kv(0, 0); CP_COMMIT();
    load_kv(1, 1); CP_COMMIT();

    CP_WAIT(1);
    __syncthreads();

    // ---- Q fragments (register-resident) via ldmatrix ----
    unsigned aqh[4][4], aql[4][4];
#pragma unroll
    for (int j = 0; j < 4; j++) {
        ldsm_x4(aqh[j], sb + (w * 16 + arow) * 72 + j * 16 + acol);
        ldsm_x4(aql[j], sb + 9216 + (w * 16 + arow) * 72 + j * 16 + acol);
    }

    float o[8][4];
#pragma unroll
    for (int n = 0; n < 8; n++)
#pragma unroll
        for (int r = 0; r < 4; r++) o[n][r] = 0.f;
    float mrow0 = -INFINITY, mrow1 = -INFINITY, lrow0 = 0.f, lrow1 = 0.f;

    const int r0 = m0 + w * 16 + qr;
    const int r1 = r0 + 8;

    for (int jt = 0; jt < kvTiles; jt++) {
        if (jt > 0) {
            if (jt + 1 < kvTiles) CP_WAIT(1);
            else                  CP_WAIT(0);
            __syncthreads();
        }
        const __nv_bfloat16* st = sb + 18432 + (jt & 1) * 18432;

        if (jt <= lastTile) {
            const int k0 = jt * 64;
            float s[8][4];
#pragma unroll
            for (int n = 0; n < 8; n++)
#pragma unroll
                for (int r = 0; r < 4; r++) s[n][r] = 0.f;

            // S = Q K^T (bf16x3)
#pragma unroll
            for (int j = 0; j < 4; j++) {
#pragma unroll
                for (int p = 0; p < 4; p++) {
                    unsigned bh[4], bl[4];
                    ldsm_x4(bh, st + (p * 16 + brow) * 72 + j * 16 + bcol);
                    ldsm_x4(bl, st + 4608 + (p * 16 + brow) * 72 + j * 16 + bcol);
                    mma16816(s[2 * p],     aqh[j], bh);
                    mma16816(s[2 * p],     aql[j], bh);
                    mma16816(s[2 * p],     aqh[j], bl);
                    mma16816(s[2 * p + 1], aqh[j], bh + 2);
                    mma16816(s[2 * p + 1], aql[j], bh + 2);
                    mma16816(s[2 * p + 1], aqh[j], bl + 2);
                }
            }

            // scale + causal mask
            const float rs = 0.125f;
            if (k0 + 63 > m0 + w * 16) {
#pragma unroll
                for (int n = 0; n < 8; n++) {
                    int c0 = k0 + n * 8 + qc;
                    s[n][0] = (c0     > r0) ? -1e30f : s[n][0] * rs;
                    s[n][1] = (c0 + 1 > r0) ? -1e30f : s[n][1] * rs;
                    s[n][2] = (c0     > r1) ? -1e30f : s[n][2] * rs;
                    s[n][3] = (c0 + 1 > r1) ? -1e30f : s[n][3] * rs;
                }
            } else {
#pragma unroll
                for (int n = 0; n < 8; n++)
#pragma unroll
                    for (int r = 0; r < 4; r++) s[n][r] *= rs;
            }

            // online softmax
            float mx0 = -1e30f, mx1 = -1e30f;
#pragma unroll
            for (int n = 0; n < 8; n++) {
                mx0 = fmaxf(mx0, fmaxf(s[n][0], s[n][1]));
                mx1 = fmaxf(mx1, fmaxf(s[n][2], s[n][3]));
            }
            mx0 = fmaxf(mx0, __shfl_xor_sync(0xffffffffu, mx0, 1));
            mx0 = fmaxf(mx0, __shfl_xor_sync(0xffffffffu, mx0, 2));
            mx1 = fmaxf(mx1, __shfl_xor_sync(0xffffffffu, mx1, 1));
            mx1 = fmaxf(mx1, __shfl_xor_sync(0xffffffffu, mx1, 2));
            float mn0 = fmaxf(mrow0, mx0), mn1 = fmaxf(mrow1, mx1);
            float cr0 = __expf(mrow0 - mn0), cr1 = __expf(mrow1 - mn1);
            float sum0 = 0.f, sum1 = 0.f;
#pragma unroll
            for (int n = 0; n < 8; n++) {
                s[n][0] = __expf(s[n][0] - mn0);
                s[n][1] = __expf(s[n][1] - mn0);
                s[n][2] = __expf(s[n][2] - mn1);
                s[n][3] = __expf(s[n][3] - mn1);
                sum0 += s[n][0] + s[n][1];
                sum1 += s[n][2] + s[n][3];
            }
            sum0 += __shfl_xor_sync(0xffffffffu, sum0, 1);
            sum0 += __shfl_xor_sync(0xffffffffu, sum0, 2);
            sum1 += __shfl_xor_sync(0xffffffffu, sum1, 1);
            sum1 += __shfl_xor_sync(0xffffffffu, sum1, 2);
            lrow0 = lrow0 * cr0 + sum0;
            lrow1 = lrow1 * cr1 + sum1;
            mrow0 = mn0; mrow1 = mn1;
#pragma unroll
            for (int n = 0; n < 8; n++) {
                o[n][0] *= cr0; o[n][1] *= cr0;
                o[n][2] *= cr1; o[n][3] *= cr1;
            }

            // P fragments in registers
            unsigned pah[4][4], pal[4][4];
#pragma unroll
            for (int j = 0; j < 4; j++) {
                split2(s[2 * j][0],     s[2 * j][1],     pah[j][0], pal[j][0]);
                split2(s[2 * j][2],     s[2 * j][3],     pah[j][1], pal[j][1]);
                split2(s[2 * j + 1][0], s[2 * j + 1][1], pah[j][2], pal[j][2]);
                split2(s[2 * j + 1][2], s[2 * j + 1][3], pah[j][3], pal[j][3]);
            }

            // O += P V (bf16x3); Vt smem is [dk][kseq]
#pragma unroll
            for (int j = 0; j < 4; j++) {
#pragma unroll
                for (int p = 0; p < 4; p++) {
                    unsigned bh[4], bl[4];
                    ldsm_x4(bh, st + 9216 + (p * 16 + brow) * 72 + j * 16 + bcol);
                    ldsm_x4(bl, st + 13824 + (p * 16 + brow) * 72 + j * 16 + bcol);
                    mma16816(o[2 * p],     pah[j], bh);
                    mma16816(o[2 * p],     pal[j], bh);
                    mma16816(o[2 * p],     pah[j], bl);
                    mma16816(o[2 * p + 1], pah[j], bh + 2);
                    mma16816(o[2 * p + 1], pal[j], bh + 2);
                    mma16816(o[2 * p + 1], pah[j], bl + 2);
                }
            }
        }

        __syncthreads();
        if (jt + 2 < kvTiles) {
            load_kv(jt & 1, jt + 2);
            CP_COMMIT();
        }
    }

    // ---- epilogue ----
    float inv0 = 1.f / lrow0, inv1 = 1.f / lrow1;
    size_t base0 = ((size_t)(b * S_LEN) + r0) * DM + h * 64;
    size_t base1 = ((size_t)(b * S_LEN) + r1) * DM + h * 64;
#pragma unroll
    for (int n = 0; n < 8; n++) {
        unsigned hh, ll;
        split2(o[n][0] * inv0, o[n][1] * inv0, hh, ll);
        *(unsigned*)(Ch_g + base0 + n * 8 + qc) = hh;
        *(unsigned*)(Cl_g + base0 + n * 8 + qc) = ll;
        split2(o[n][2] * inv1, o[n][3] * inv1, hh, ll);
        *(unsigned*)(Ch_g + base1 + n * 8 + qc) = hh;
        *(unsigned*)(Cl_g + base1 + n * 8 + qc) = ll;
    }
}

// ---------------------------------------------------------------------------
// Launch
// ---------------------------------------------------------------------------
extern "C" void kernel_launch(void* const* d_in, const int* in_sizes, int n_in,
                              void* d_out, int out_size)
{
    (void)in_sizes; (void)n_in; (void)out_size;
    const float* x  = (const float*)d_in[0];
    const float* Wq = (const float*)d_in[2];
    const float* bq = (const float*)d_in[3];
    const float* Wk = (const float*)d_in[4];
    const float* bk = (const float*)d_in[5];
    const float* Wv = (const float*)d_in[6];
    const float* bv = (const float*)d_in[7];
    const float* Wo = (const float*)d_in[8];
    const float* bo = (const float*)d_in[9];
    float* out = (float*)d_out;

    __nv_bfloat16 *xh, *xl, *Qh, *Ql, *Kh, *Kl, *Vth, *Vtl, *Ch, *Cl;
    __nv_bfloat16 *Wqh, *Wql, *Wkh, *Wkl, *Wvh, *Wvl, *Woh, *Wol;
    cudaGetSymbolAddress((void**)&xh, g_xh);   cudaGetSymbolAddress((void**)&xl, g_xl);
    cudaGetSymbolAddress((void**)&Qh, g_Qh);   cudaGetSymbolAddress((void**)&Ql, g_Ql);
    cudaGetSymbolAddress((void**)&Kh, g_Kh);   cudaGetSymbolAddress((void**)&Kl, g_Kl);
    cudaGetSymbolAddress((void**)&Vth, g_Vth); cudaGetSymbolAddress((void**)&Vtl, g_Vtl);
    cudaGetSymbolAddress((void**)&Ch, g_Ch);   cudaGetSymbolAddress((void**)&Cl, g_Cl);
    cudaGetSymbolAddress((void**)&Wqh, g_Wqh); cudaGetSymbolAddress((void**)&Wql, g_Wql);
    cudaGetSymbolAddress((void**)&Wkh, g_Wkh); cudaGetSymbolAddress((void**)&Wkl, g_Wkl);
    cudaGetSymbolAddress((void**)&Wvh, g_Wvh); cudaGetSymbolAddress((void**)&Wvl, g_Wvl);
    cudaGetSymbolAddress((void**)&Woh, g_Woh); cudaGetSymbolAddress((void**)&Wol, g_Wol);

    cudaFuncSetAttribute(gemm_bf16x3,
                         cudaFuncAttributeMaxDynamicSharedMemorySize, GEMM_SMEM);
    cudaFuncSetAttribute(gqa_flash_mma,
                         cudaFuncAttributeMaxDynamicSharedMemorySize, FL_SMEM);

    const int NX = MROWS * DM;

    // prep
    split_kernel<<<NX / 4 / 256, 256>>>(x, xh, xl, NX);
    transpose_split<<<dim3(DM / 32,  DM / 32), dim3(32, 8)>>>(Wq, Wqh, Wql, DM, DM);
    transpose_split<<<dim3(KVW / 32, DM / 32), dim3(32, 8)>>>(Wk, Wkh, Wkl, DM, KVW);
    transpose_split<<<dim3(KVW / 32, DM / 32), dim3(32, 8)>>>(Wv, Wvh, Wvl, DM, KVW);
    transpose_split<<<dim3(DM / 32,  DM / 32), dim3(32, 8)>>>(Wo, Woh, Wol, DM, DM);

    // projections
    gemm_bf16x3<<<dim3(DM / 128,  MROWS / 128), 256, GEMM_SMEM>>>(
        xh, xl, Wqh, Wql, bq, nullptr, Qh, Ql, 1, MROWS, DM, DM);
    gemm_bf16x3<<<dim3(KVW / 128, MROWS / 128), 256, GEMM_SMEM>>>(
        xh, xl, Wkh, Wkl, bk, nullptr, Kh, Kl, 1, MROWS, KVW, DM);
    gemm_bf16x3<<<dim3(KVW / 128, MROWS / 128), 256, GEMM_SMEM>>>(
        xh, xl, Wvh, Wvl, bv, nullptr, Vth, Vtl, 2, MROWS, KVW, DM);

    // attention
    gqa_flash_mma<<<dim3(S_LEN / 128, NH, B_SZ), 256, FL_SMEM>>>(
        Qh, Ql, Kh, Kl, Vth, Vtl, Ch, Cl);

    // output projection (fp32 out)
    gemm_bf16x3<<<dim3(DM / 128, MROWS / 128), 256, GEMM_SMEM>>>(
        Ch, Cl, Woh, Wol, bo, out, nullptr, nullptr, 0, MROWS, DM, DM);
}

// round 8
// speedup vs baseline: 2.7178x; 1.0003x over previous
#include <cuda_runtime.h>
#include <cuda_bf16.h>
#include <cstdint>
#include <math.h>

#define B_SZ   2
#define S_LEN  2048
#define DM     2048
#define NH     32
#define NKV    8
#define DK     64
#define KVW    (NKV * DK)      // 512
#define MROWS  (B_SZ * S_LEN)  // 4096

// ---------------- scratch (device globals; no allocation allowed) ----------
__device__ __nv_bfloat16 g_xh[MROWS * DM],  g_xl[MROWS * DM];
__device__ __nv_bfloat16 g_Qh[MROWS * DM],  g_Ql[MROWS * DM];
__device__ __nv_bfloat16 g_Kh[MROWS * KVW], g_Kl[MROWS * KVW];
__device__ __nv_bfloat16 g_Vth[B_SZ * KVW * S_LEN], g_Vtl[B_SZ * KVW * S_LEN]; // [b][dk][s]
__device__ __nv_bfloat16 g_Ch[MROWS * DM],  g_Cl[MROWS * DM];
__device__ __nv_bfloat16 g_Wqh[DM * DM],   g_Wql[DM * DM];    // stored [N][K]
__device__ __nv_bfloat16 g_Wkh[KVW * DM],  g_Wkl[KVW * DM];
__device__ __nv_bfloat16 g_Wvh[KVW * DM],  g_Wvl[KVW * DM];
__device__ __nv_bfloat16 g_Woh[DM * DM],   g_Wol[DM * DM];

// ---------------------------------------------------------------------------
// helpers
// ---------------------------------------------------------------------------
__device__ __forceinline__ void cp16(void* s, const void* g) {
    unsigned sa = (unsigned)__cvta_generic_to_shared(s);
    asm volatile("cp.async.cg.shared.global [%0], [%1], 16;\n" :: "r"(sa), "l"(g));
}
#define CP_COMMIT() asm volatile("cp.async.commit_group;\n")
#define CP_WAIT(n)  asm volatile("cp.async.wait_group %0;\n" :: "n"(n) : "memory")

__device__ __forceinline__ void mma16816(float* c, const unsigned* a, const unsigned* b) {
    asm volatile(
        "mma.sync.aligned.m16n8k16.row.col.f32.bf16.bf16.f32 "
        "{%0,%1,%2,%3}, {%4,%5,%6,%7}, {%8,%9}, {%0,%1,%2,%3};\n"
        : "+f"(c[0]), "+f"(c[1]), "+f"(c[2]), "+f"(c[3])
        : "r"(a[0]), "r"(a[1]), "r"(a[2]), "r"(a[3]), "r"(b[0]), "r"(b[1]));
}

__device__ __forceinline__ void ldsm_x4(unsigned* r, const void* p) {
    unsigned a = (unsigned)__cvta_generic_to_shared(p);
    asm volatile("ldmatrix.sync.aligned.m8n8.x4.shared.b16 {%0,%1,%2,%3}, [%4];\n"
                 : "=r"(r[0]), "=r"(r[1]), "=r"(r[2]), "=r"(r[3]) : "r"(a));
}

// pack two fp32 into bf16x2 hi + residual lo
__device__ __forceinline__ void split2(float v0, float v1, unsigned& hi, unsigned& lo) {
    __nv_bfloat162 h = __floats2bfloat162_rn(v0, v1);
    __nv_bfloat162 l = __floats2bfloat162_rn(v0 - __bfloat162float(h.x),
                                             v1 - __bfloat162float(h.y));
    hi = *(unsigned*)&h;
    lo = *(unsigned*)&l;
}

// ---------------------------------------------------------------------------
// split fp32 -> bf16 hi/lo (row-major, same layout)
// ---------------------------------------------------------------------------
__global__ void split_kernel(const float* __restrict__ s,
                             __nv_bfloat16* __restrict__ h,
                             __nv_bfloat16* __restrict__ lo, int n)
{
    int i = (blockIdx.x * blockDim.x + threadIdx.x) * 4;
    if (i >= n) return;
    float4 v = *(const float4*)(s + i);
    unsigned h0, l0, h1, l1;
    split2(v.x, v.y, h0, l0);
    split2(v.z, v.w, h1, l1);
    *(unsigned*)(h + i)      = h0;
    *(unsigned*)(h + i + 2)  = h1;
    *(unsigned*)(lo + i)     = l0;
    *(unsigned*)(lo + i + 2) = l1;
}

// ---------------------------------------------------------------------------
// transpose + split: W [K][N] fp32 -> Th, Tl [N][K] bf16
// ---------------------------------------------------------------------------
__global__ void transpose_split(const float* __restrict__ W,
                                __nv_bfloat16* __restrict__ Th,
                                __nv_bfloat16* __restrict__ Tl, int K, int N)
{
    __shared__ float t[32][33];
    int bx = blockIdx.x * 32;   // n
    int by = blockIdx.y * 32;   // k
    int tx = threadIdx.x, ty = threadIdx.y;
#pragma unroll
    for (int i = 0; i < 32; i += 8)
        t[ty + i][tx] = W[(size_t)(by + ty + i) * N + bx + tx];
    __syncthreads();
#pragma unroll
    for (int i = 0; i < 32; i += 8) {
        float v = t[tx][ty + i];
        size_t o = (size_t)(bx + ty + i) * K + by + tx;
        __nv_bfloat16 h = __float2bfloat16(v);
        Th[o] = h;
        Tl[o] = __float2bfloat16(v - __bfloat162float(h));
    }
}

// ---------------------------------------------------------------------------
// bf16x3 tensor-core GEMM, 128x128x32 tiles, ldmatrix fragment feed.
// epilogue modes: 0 fp32+bias; 1 split bf16 row-major; 2 split bf16 transposed
// ---------------------------------------------------------------------------
#define GEMM_SMEM 81920

__global__ __launch_bounds__(256) void gemm_bf16x3(
    const __nv_bfloat16* __restrict__ Ah, const __nv_bfloat16* __restrict__ Al,
    const __nv_bfloat16* __restrict__ Bh, const __nv_bfloat16* __restrict__ Bl,
    const float* __restrict__ bias, float* __restrict__ Cf,
    __nv_bfloat16* __restrict__ Coh, __nv_bfloat16* __restrict__ Col,
    int mode, int M, int N, int K)
{
    extern __shared__ __nv_bfloat16 sm[];
    const int tid = threadIdx.x;
    const int bm = blockIdx.y * 128;
    const int bn = blockIdx.x * 128;
    const int T = K >> 5;

    auto load_stage = [&](int s, int k0) {
        __nv_bfloat16* base = sm + s * 20480;
#pragma unroll
        for (int t = 0; t < 2; t++) {
            int c = tid + t * 256;
            int row = c >> 2;
            int seg = (c & 3) << 3;
            size_t ga = (size_t)(bm + row) * K + k0 + seg;
            size_t gb = (size_t)(bn + row) * K + k0 + seg;
            int so = row * 40 + seg;
            cp16(base + so,         Ah + ga);
            cp16(base + 5120 + so,  Al + ga);
            cp16(base + 10240 + so, Bh + gb);
            cp16(base + 15360 + so, Bl + gb);
        }
    };

    const int w = tid >> 5, l = tid & 31;
    const int wm = (w >> 2) * 64;
    const int wn = (w & 3) * 32;
    const int qr = l >> 2;
    const int qc = (l & 3) * 2;
    // ldmatrix lane addressing
    const int arow = (l & 7) + ((l >> 3) & 1) * 8;   // A: row within m16
    const int acol = (l >> 4) * 8;                   // A: col offset (0/8)
    const int brow = (l & 7) + ((l >> 4) & 1) * 8;   // B: row within n16 (2 n-tiles)
    const int bcol = ((l >> 3) & 1) * 8;             // B: col offset (0/8)

    float acc[4][4][4];
#pragma unroll
    for (int mi = 0; mi < 4; mi++)
#pragma unroll
        for (int ni = 0; ni < 4; ni++)
#pragma unroll
            for (int r = 0; r < 4; r++) acc[mi][ni][r] = 0.f;

    load_stage(0, 0);  CP_COMMIT();
    load_stage(1, 32); CP_COMMIT();

    for (int i = 0; i < T; i++) {
        if (i + 1 < T) CP_WAIT(1);
        else           CP_WAIT(0);
        __syncthreads();

        const __nv_bfloat16* Ahs = sm + (i & 1) * 20480;
        const __nv_bfloat16* Als = Ahs + 5120;
        const __nv_bfloat16* Bhs = Ahs + 10240;
        const __nv_bfloat16* Bls = Ahs + 15360;

#pragma unroll
        for (int ks = 0; ks < 32; ks += 16) {
            unsigned ah[4][4], al[4][4];
#pragma unroll
            for (int mi = 0; mi < 4; mi++) {
                ldsm_x4(ah[mi], Ahs + (wm + mi * 16 + arow) * 40 + ks + acol);
                ldsm_x4(al[mi], Als + (wm + mi * 16 + arow) * 40 + ks + acol);
            }
#pragma unroll
            for (int p = 0; p < 2; p++) {
                unsigned bh[4], bl[4];
                ldsm_x4(bh, Bhs + (wn + p * 16 + brow) * 40 + ks + bcol);
                ldsm_x4(bl, Bls + (wn + p * 16 + brow) * 40 + ks + bcol);
#pragma unroll
                for (int mi = 0; mi < 4; mi++) {
                    mma16816(acc[mi][2 * p],     ah[mi], bh);
                    mma16816(acc[mi][2 * p],     al[mi], bh);
                    mma16816(acc[mi][2 * p],     ah[mi], bl);
                    mma16816(acc[mi][2 * p + 1], ah[mi], bh + 2);
                    mma16816(acc[mi][2 * p + 1], al[mi], bh + 2);
                    mma16816(acc[mi][2 * p + 1], ah[mi], bl + 2);
                }
            }
        }
        __syncthreads();
        if (i + 2 < T) {
            load_stage(i & 1, (i + 2) * 32);
            CP_COMMIT();
        }
    }

#pragma unroll
    for (int mi = 0; mi < 4; mi++) {
#pragma unroll
        for (int ni = 0; ni < 4; ni++) {
            int r  = bm + wm + mi * 16 + qr;
            int cc = bn + wn + ni * 8 + qc;
            float b0 = bias[cc], b1 = bias[cc + 1];
            float v0 = acc[mi][ni][0] + b0, v1 = acc[mi][ni][1] + b1;
            float v2 = acc[mi][ni][2] + b0, v3 = acc[mi][ni][3] + b1;
            if (mode == 0) {
                float2 a = {v0, v1}, bb = {v2, v3};
                *(float2*)(Cf + (size_t)r * N + cc)       = a;
                *(float2*)(Cf + (size_t)(r + 8) * N + cc) = bb;
            } else if (mode == 1) {
                unsigned h0, l0, h1, l1;
                split2(v0, v1, h0, l0);
                split2(v2, v3, h1, l1);
                *(unsigned*)(Coh + (size_t)r * N + cc)       = h0;
                *(unsigned*)(Col + (size_t)r * N + cc)       = l0;
                *(unsigned*)(Coh + (size_t)(r + 8) * N + cc) = h1;
                *(unsigned*)(Col + (size_t)(r + 8) * N + cc) = l1;
            } else {
                int bb2 = r >> 11;
                int sl  = r & (S_LEN - 1);
                size_t base = ((size_t)bb2 * KVW + cc) * S_LEN;
                __nv_bfloat16 h, lo2;
                h = __float2bfloat16(v0); lo2 = __float2bfloat16(v0 - __bfloat162float(h));
                Coh[base + sl] = h; Col[base + sl] = lo2;
                h = __float2bfloat16(v1); lo2 = __float2bfloat16(v1 - __bfloat162float(h));
                Coh[base + S_LEN + sl] = h; Col[base + S_LEN + sl] = lo2;
                h = __float2bfloat16(v2); lo2 = __float2bfloat16(v2 - __bfloat162float(h));
                Coh[base + sl + 8] = h; Col[base + sl + 8] = lo2;
                h = __float2bfloat16(v3); lo2 = __float2bfloat16(v3 - __bfloat162float(h));
                Coh[base + S_LEN + sl + 8] = h; Col[base + S_LEN + sl + 8] = lo2;
            }
        }
    }
}

// ---------------------------------------------------------------------------
// Tensor-core flash attention (causal, GQA), bf16x3, ldmatrix fragment feed.
// ---------------------------------------------------------------------------
#define FL_SMEM ((18432 + 2 * 18432) * 2)   // 110592 bytes

__global__ __launch_bounds__(256) void gqa_flash_mma(
    const __nv_bfloat16* __restrict__ Qh_g, const __nv_bfloat16* __restrict__ Ql_g,
    const __nv_bfloat16* __restrict__ Kh_g, const __nv_bfloat16* __restrict__ Kl_g,
    const __nv_bfloat16* __restrict__ Vth_g, const __nv_bfloat16* __restrict__ Vtl_g,
    __nv_bfloat16* __restrict__ Ch_g, __nv_bfloat16* __restrict__ Cl_g)
{
    extern __shared__ __nv_bfloat16 sb[];
    const int tid = threadIdx.x;
    const int w = tid >> 5, l = tid & 31;
    const int qr = l >> 2, qc = (l & 3) * 2;
    const int arow = (l & 7) + ((l >> 3) & 1) * 8;
    const int acol = (l >> 4) * 8;
    const int brow = (l & 7) + ((l >> 4) & 1) * 8;
    const int bcol = ((l >> 3) & 1) * 8;
    const int mtile = blockIdx.x, h = blockIdx.y, b = blockIdx.z;
    const int kvh = h >> 2;
    const int m0 = mtile * 128;
    const int kvTiles = 2 * mtile + 2;
    const int lastTile = 2 * mtile + (w >> 2);   // per-warp causal skip

    // ---- Q loads ----
    const __nv_bfloat16* Qph = Qh_g + ((size_t)(b * S_LEN + m0)) * DM + h * 64;
    const __nv_bfloat16* Qpl = Ql_g + ((size_t)(b * S_LEN + m0)) * DM + h * 64;
#pragma unroll
    for (int t = 0; t < 4; t++) {
        int idx = tid + t * 256;
        int row = idx >> 3, seg = (idx & 7) * 8;
        cp16(sb + row * 72 + seg,        Qph + (size_t)row * DM + seg);
        cp16(sb + 9216 + row * 72 + seg, Qpl + (size_t)row * DM + seg);
    }

    auto load_kv = [&](int sidx, int jt) {
        __nv_bfloat16* st = sb + 18432 + sidx * 18432;
        const int k0 = jt * 64;
        const __nv_bfloat16* Kgh = Kh_g + ((size_t)(b * S_LEN + k0)) * KVW + kvh * 64;
        const __nv_bfloat16* Kgl = Kl_g + ((size_t)(b * S_LEN + k0)) * KVW + kvh * 64;
        const __nv_bfloat16* Vgh = Vth_g + ((size_t)b * KVW + kvh * 64) * S_LEN + k0;
        const __nv_bfloat16* Vgl = Vtl_g + ((size_t)b * KVW + kvh * 64) * S_LEN + k0;
#pragma unroll
        for (int t = 0; t < 2; t++) {
            int idx = tid + t * 256;
            int row = idx >> 3, seg = (idx & 7) * 8;
            cp16(st + row * 72 + seg,         Kgh + (size_t)row * KVW + seg);
            cp16(st + 4608 + row * 72 + seg,  Kgl + (size_t)row * KVW + seg);
            cp16(st + 9216 + row * 72 + seg,  Vgh + (size_t)row * S_LEN + seg);
            cp16(st + 13824 + row * 72 + seg, Vgl + (size_t)row * S_LEN + seg);
        }
    };

    load_kv(0, 0); CP_COMMIT();
    load_kv(1, 1); CP_COMMIT();

    CP_WAIT(1);
    __syncthreads();

    // ---- Q fragments (register-resident) via ldmatrix ----
    unsigned aqh[4][4], aql[4][4];
#pragma unroll
    for (int j = 0; j < 4; j++) {
        ldsm_x4(aqh[j], sb + (w * 16 + arow) * 72 + j * 16 + acol);
        ldsm_x4(aql[j], sb + 9216 + (w * 16 + arow) * 72 + j * 16 + acol);
    }

    float o[8][4];
#pragma unroll
    for (int n = 0; n < 8; n++)
#pragma unroll
        for (int r = 0; r < 4; r++) o[n][r] = 0.f;
    float mrow0 = -INFINITY, mrow1 = -INFINITY, lrow0 = 0.f, lrow1 = 0.f;

    const int r0 = m0 + w * 16 + qr;
    const int r1 = r0 + 8;

    for (int jt = 0; jt < kvTiles; jt++) {
        if (jt > 0) {
            if (jt + 1 < kvTiles) CP_WAIT(1);
            else                  CP_WAIT(0);
            __syncthreads();
        }
        const __nv_bfloat16* st = sb + 18432 + (jt & 1) * 18432;

        if (jt <= lastTile) {
            const int k0 = jt * 64;
            float s[8][4];
#pragma unroll
            for (int n = 0; n < 8; n++)
#pragma unroll
                for (int r = 0; r < 4; r++) s[n][r] = 0.f;

            // S = Q K^T (bf16x3)
#pragma unroll
            for (int j = 0; j < 4; j++) {
#pragma unroll
                for (int p = 0; p < 4; p++) {
                    unsigned bh[4], bl[4];
                    ldsm_x4(bh, st + (p * 16 + brow) * 72 + j * 16 + bcol);
                    ldsm_x4(bl, st + 4608 + (p * 16 + brow) * 72 + j * 16 + bcol);
                    mma16816(s[2 * p],     aqh[j], bh);
                    mma16816(s[2 * p],     aql[j], bh);
                    mma16816(s[2 * p],     aqh[j], bl);
                    mma16816(s[2 * p + 1], aqh[j], bh + 2);
                    mma16816(s[2 * p + 1], aql[j], bh + 2);
                    mma16816(s[2 * p + 1], aqh[j], bl + 2);
                }
            }

            // scale + causal mask
            const float rs = 0.125f;
            if (k0 + 63 > m0 + w * 16) {
#pragma unroll
                for (int n = 0; n < 8; n++) {
                    int c0 = k0 + n * 8 + qc;
                    s[n][0] = (c0     > r0) ? -1e30f : s[n][0] * rs;
                    s[n][1] = (c0 + 1 > r0) ? -1e30f : s[n][1] * rs;
                    s[n][2] = (c0     > r1) ? -1e30f : s[n][2] * rs;
                    s[n][3] = (c0 + 1 > r1) ? -1e30f : s[n][3] * rs;
                }
            } else {
#pragma unroll
                for (int n = 0; n < 8; n++)
#pragma unroll
                    for (int r = 0; r < 4; r++) s[n][r] *= rs;
            }

            // online softmax
            float mx0 = -1e30f, mx1 = -1e30f;
#pragma unroll
            for (int n = 0; n < 8; n++) {
                mx0 = fmaxf(mx0, fmaxf(s[n][0], s[n][1]));
                mx1 = fmaxf(mx1, fmaxf(s[n][2], s[n][3]));
            }
            mx0 = fmaxf(mx0, __shfl_xor_sync(0xffffffffu, mx0, 1));
            mx0 = fmaxf(mx0, __shfl_xor_sync(0xffffffffu, mx0, 2));
            mx1 = fmaxf(mx1, __shfl_xor_sync(0xffffffffu, mx1, 1));
            mx1 = fmaxf(mx1, __shfl_xor_sync(0xffffffffu, mx1, 2));
            float mn0 = fmaxf(mrow0, mx0), mn1 = fmaxf(mrow1, mx1);
            float cr0 = __expf(mrow0 - mn0), cr1 = __expf(mrow1 - mn1);
            float sum0 = 0.f, sum1 = 0.f;
#pragma unroll
            for (int n = 0; n < 8; n++) {
                s[n][0] = __expf(s[n][0] - mn0);
                s[n][1] = __expf(s[n][1] - mn0);
                s[n][2] = __expf(s[n][2] - mn1);
                s[n][3] = __expf(s[n][3] - mn1);
                sum0 += s[n][0] + s[n][1];
                sum1 += s[n][2] + s[n][3];
            }
            sum0 += __shfl_xor_sync(0xffffffffu, sum0, 1);
            sum0 += __shfl_xor_sync(0xffffffffu, sum0, 2);
            sum1 += __shfl_xor_sync(0xffffffffu, sum1, 1);
            sum1 += __shfl_xor_sync(0xffffffffu, sum1, 2);
            lrow0 = lrow0 * cr0 + sum0;
            lrow1 = lrow1 * cr1 + sum1;
            mrow0 = mn0; mrow1 = mn1;
#pragma unroll
            for (int n = 0; n < 8; n++) {
                o[n][0] *= cr0; o[n][1] *= cr0;
                o[n][2] *= cr1; o[n][3] *= cr1;
            }

            // P fragments in registers
            unsigned pah[4][4], pal[4][4];
#pragma unroll
            for (int j = 0; j < 4; j++) {
                split2(s[2 * j][0],     s[2 * j][1],     pah[j][0], pal[j][0]);
                split2(s[2 * j][2],     s[2 * j][3],     pah[j][1], pal[j][1]);
                split2(s[2 * j + 1][0], s[2 * j + 1][1], pah[j][2], pal[j][2]);
                split2(s[2 * j + 1][2], s[2 * j + 1][3], pah[j][3], pal[j][3]);
            }

            // O += P V (bf16x3); Vt smem is [dk][kseq]
#pragma unroll
            for (int j = 0; j < 4; j++) {
#pragma unroll
                for (int p = 0; p < 4; p++) {
                    unsigned bh[4], bl[4];
                    ldsm_x4(bh, st + 9216 + (p * 16 + brow) * 72 + j * 16 + bcol);
                    ldsm_x4(bl, st + 13824 + (p * 16 + brow) * 72 + j * 16 + bcol);
                    mma16816(o[2 * p],     pah[j], bh);
                    mma16816(o[2 * p],     pal[j], bh);
                    mma16816(o[2 * p],     pah[j], bl);
                    mma16816(o[2 * p + 1], pah[j], bh + 2);
                    mma16816(o[2 * p + 1], pal[j], bh + 2);
                    mma16816(o[2 * p + 1], pah[j], bl + 2);
                }
            }
        }

        __syncthreads();
        if (jt + 2 < kvTiles) {
            load_kv(jt & 1, jt + 2);
            CP_COMMIT();
        }
    }

    // ---- epilogue ----
    float inv0 = 1.f / lrow0, inv1 = 1.f / lrow1;
    size_t base0 = ((size_t)(b * S_LEN) + r0) * DM + h * 64;
    size_t base1 = ((size_t)(b * S_LEN) + r1) * DM + h * 64;
#pragma unroll
    for (int n = 0; n < 8; n++) {
        unsigned hh, ll;
        split2(o[n][0] * inv0, o[n][1] * inv0, hh, ll);
        *(unsigned*)(Ch_g + base0 + n * 8 + qc) = hh;
        *(unsigned*)(Cl_g + base0 + n * 8 + qc) = ll;
        split2(o[n][2] * inv1, o[n][3] * inv1, hh, ll);
        *(unsigned*)(Ch_g + base1 + n * 8 + qc) = hh;
        *(unsigned*)(Cl_g + base1 + n * 8 + qc) = ll;
    }
}

// ---------------------------------------------------------------------------
// Launch
// ---------------------------------------------------------------------------
extern "C" void kernel_launch(void* const* d_in, const int* in_sizes, int n_in,
                              void* d_out, int out_size)
{
    (void)in_sizes; (void)n_in; (void)out_size;
    const float* x  = (const float*)d_in[0];
    const float* Wq = (const float*)d_in[2];
    const float* bq = (const float*)d_in[3];
    const float* Wk = (const float*)d_in[4];
    const float* bk = (const float*)d_in[5];
    const float* Wv = (const float*)d_in[6];
    const float* bv = (const float*)d_in[7];
    const float* Wo = (const float*)d_in[8];
    const float* bo = (const float*)d_in[9];
    float* out = (float*)d_out;

    __nv_bfloat16 *xh, *xl, *Qh, *Ql, *Kh, *Kl, *Vth, *Vtl, *Ch, *Cl;
    __nv_bfloat16 *Wqh, *Wql, *Wkh, *Wkl, *Wvh, *Wvl, *Woh, *Wol;
    cudaGetSymbolAddress((void**)&xh, g_xh);   cudaGetSymbolAddress((void**)&xl, g_xl);
    cudaGetSymbolAddress((void**)&Qh, g_Qh);   cudaGetSymbolAddress((void**)&Ql, g_Ql);
    cudaGetSymbolAddress((void**)&Kh, g_Kh);   cudaGetSymbolAddress((void**)&Kl, g_Kl);
    cudaGetSymbolAddress((void**)&Vth, g_Vth); cudaGetSymbolAddress((void**)&Vtl, g_Vtl);
    cudaGetSymbolAddress((void**)&Ch, g_Ch);   cudaGetSymbolAddress((void**)&Cl, g_Cl);
    cudaGetSymbolAddress((void**)&Wqh, g_Wqh); cudaGetSymbolAddress((void**)&Wql, g_Wql);
    cudaGetSymbolAddress((void**)&Wkh, g_Wkh); cudaGetSymbolAddress((void**)&Wkl, g_Wkl);
    cudaGetSymbolAddress((void**)&Wvh, g_Wvh); cudaGetSymbolAddress((void**)&Wvl, g_Wvl);
    cudaGetSymbolAddress((void**)&Woh, g_Woh); cudaGetSymbolAddress((void**)&Wol, g_Wol);

    cudaFuncSetAttribute(gemm_bf16x3,
                         cudaFuncAttributeMaxDynamicSharedMemorySize, GEMM_SMEM);
    cudaFuncSetAttribute(gqa_flash_mma,
                         cudaFuncAttributeMaxDynamicSharedMemorySize, FL_SMEM);

    const int NX = MROWS * DM;

    // prep
    split_kernel<<<NX / 4 / 256, 256>>>(x, xh, xl, NX);
    transpose_split<<<dim3(DM / 32,  DM / 32), dim3(32, 8)>>>(Wq, Wqh, Wql, DM, DM);
    transpose_split<<<dim3(KVW / 32, DM / 32), dim3(32, 8)>>>(Wk, Wkh, Wkl, DM, KVW);
    transpose_split<<<dim3(KVW / 32, DM / 32), dim3(32, 8)>>>(Wv, Wvh, Wvl, DM, KVW);
    transpose_split<<<dim3(DM / 32,  DM / 32), dim3(32, 8)>>>(Wo, Woh, Wol, DM, DM);

    // projections
    gemm_bf16x3<<<dim3(DM / 128,  MROWS / 128), 256, GEMM_SMEM>>>(
        xh, xl, Wqh, Wql, bq, nullptr, Qh, Ql, 1, MROWS, DM, DM);
    gemm_bf16x3<<<dim3(KVW / 128, MROWS / 128), 256, GEMM_SMEM>>>(
        xh, xl, Wkh, Wkl, bk, nullptr, Kh, Kl, 1, MROWS, KVW, DM);
    gemm_bf16x3<<<dim3(KVW / 128, MROWS / 128), 256, GEMM_SMEM>>>(
        xh, xl, Wvh, Wvl, bv, nullptr, Vth, Vtl, 2, MROWS, KVW, DM);

    // attention
    gqa_flash_mma<<<dim3(S_LEN / 128, NH, B_SZ), 256, FL_SMEM>>>(
        Qh, Ql, Kh, Kl, Vth, Vtl, Ch, Cl);

    // output projection (fp32 out)
    gemm_bf16x3<<<dim3(DM / 128, MROWS / 128), 256, GEMM_SMEM>>>(
        Ch, Cl, Woh, Wol, bo, out, nullptr, nullptr, 0, MROWS, DM, DM);
}

// round 10
// speedup vs baseline: 4.0386x; 1.4860x over previous
#include <cuda_runtime.h>
#include <cuda_fp16.h>
#include <cstdint>
#include <math.h>

#define B_SZ   2
#define S_LEN  2048
#define DM     2048
#define NH     32
#define NKV    8
#define DK     64
#define KVW    (NKV * DK)      // 512
#define MROWS  (B_SZ * S_LEN)  // 4096
#define NCAT   3072            // Q(2048) + K(512) + V(512)

// ---------------- scratch ----------------
__device__ __half g_xh[MROWS * DM], g_xl[MROWS * DM];
__device__ __half g_Qh[MROWS * DM], g_Ql[MROWS * DM];
__device__ __half g_Kh[MROWS * KVW];
__device__ __half g_Vth[B_SZ * KVW * S_LEN];      // [b][dk][s]
__device__ __half g_Ch[MROWS * DM], g_Cl[MROWS * DM];
__device__ __half g_Wcat[NCAT * DM];              // [N][K] concat Q|K|V weights (hi)
__device__ __half g_Woh[DM * DM];
__device__ float  g_bcat[NCAT];

// ---------------- helpers ----------------
__device__ __forceinline__ void cp16(void* s, const void* g) {
    unsigned sa = (unsigned)__cvta_generic_to_shared(s);
    asm volatile("cp.async.cg.shared.global [%0], [%1], 16;\n" :: "r"(sa), "l"(g));
}
#define CP_COMMIT() asm volatile("cp.async.commit_group;\n")
#define CP_WAIT(n)  asm volatile("cp.async.wait_group %0;\n" :: "n"(n) : "memory")

__device__ __forceinline__ void mma16816(float* c, const unsigned* a, const unsigned* b) {
    asm volatile(
        "mma.sync.aligned.m16n8k16.row.col.f32.f16.f16.f32 "
        "{%0,%1,%2,%3}, {%4,%5,%6,%7}, {%8,%9}, {%0,%1,%2,%3};\n"
        : "+f"(c[0]), "+f"(c[1]), "+f"(c[2]), "+f"(c[3])
        : "r"(a[0]), "r"(a[1]), "r"(a[2]), "r"(a[3]), "r"(b[0]), "r"(b[1]));
}
__device__ __forceinline__ void ldsm_x4(unsigned* r, const void* p) {
    unsigned a = (unsigned)__cvta_generic_to_shared(p);
    asm volatile("ldmatrix.sync.aligned.m8n8.x4.shared.b16 {%0,%1,%2,%3}, [%4];\n"
                 : "=r"(r[0]), "=r"(r[1]), "=r"(r[2]), "=r"(r[3]) : "r"(a));
}
__device__ __forceinline__ void split2h(float v0, float v1, unsigned& hi, unsigned& lo) {
    __half2 h = __floats2half2_rn(v0, v1);
    __half2 l = __floats2half2_rn(v0 - __low2float(h), v1 - __high2float(h));
    hi = *(unsigned*)&h;
    lo = *(unsigned*)&l;
}

// ---------------- prep kernels ----------------
__global__ void split_kernel(const float* __restrict__ s,
                             __half* __restrict__ h, __half* __restrict__ lo, int n)
{
    int i = (blockIdx.x * blockDim.x + threadIdx.x) * 4;
    if (i >= n) return;
    float4 v = *(const float4*)(s + i);
    unsigned h0, l0, h1, l1;
    split2h(v.x, v.y, h0, l0);
    split2h(v.z, v.w, h1, l1);
    *(unsigned*)(h + i) = h0;  *(unsigned*)(h + i + 2) = h1;
    *(unsigned*)(lo + i) = l0; *(unsigned*)(lo + i + 2) = l1;
}

// W [K][N] fp32 -> T [N][K] fp16 (hi only)
__global__ void transpose_half(const float* __restrict__ W, __half* __restrict__ T,
                               int K, int N)
{
    __shared__ float t[32][33];
    int bx = blockIdx.x * 32, by = blockIdx.y * 32;
    int tx = threadIdx.x, ty = threadIdx.y;
#pragma unroll
    for (int i = 0; i < 32; i += 8)
        t[ty + i][tx] = W[(size_t)(by + ty + i) * N + bx + tx];
    __syncthreads();
#pragma unroll
    for (int i = 0; i < 32; i += 8)
        T[(size_t)(bx + ty + i) * K + by + tx] = __float2half_rn(t[tx][ty + i]);
}

__global__ void bias_concat(const float* __restrict__ bq, const float* __restrict__ bk,
                            const float* __restrict__ bv, float* __restrict__ bc)
{
    int i = blockIdx.x * blockDim.x + threadIdx.x;
    if (i < 2048)      bc[i] = bq[i];
    else if (i < 2560) bc[i] = bk[i - 2048];
    else if (i < 3072) bc[i] = bv[i - 2560];
}

// ---------------------------------------------------------------------------
// fp16x2 tensor-core GEMM: C = (Ah+Al)[M,K] @ Bh^T[N,K] + bias
// 128x128x32 tiles, 8 warps, ldmatrix feed, 2-stage cp.async.
// mode 0: fp32 out (O projection). mode 1: fused QKV routing by column.
// smem/stage: Ah,Al,Bh = 3 x 128x40 halves = 30720B; 2 stages = 61440B
// ---------------------------------------------------------------------------
#define GEMM_SMEM 61440

__global__ __launch_bounds__(256) void gemm_fp16x2(
    const __half* __restrict__ Ah, const __half* __restrict__ Al,
    const __half* __restrict__ Bh, const float* __restrict__ bias,
    float* __restrict__ Cf,
    __half* __restrict__ Qh, __half* __restrict__ Ql,
    __half* __restrict__ Kh, __half* __restrict__ Vth,
    int mode, int N, int K)
{
    extern __shared__ __half sm[];
    const int tid = threadIdx.x;
    const int bm = blockIdx.y * 128;
    const int bn = blockIdx.x * 128;
    const int T = K >> 5;

    auto load_stage = [&](int s, int k0) {
        __half* base = sm + s * 15360;
#pragma unroll
        for (int t = 0; t < 2; t++) {
            int c = tid + t * 256;
            int row = c >> 2;
            int seg = (c & 3) << 3;
            size_t ga = (size_t)(bm + row) * K + k0 + seg;
            size_t gb = (size_t)(bn + row) * K + k0 + seg;
            int so = row * 40 + seg;
            cp16(base + so,         Ah + ga);
            cp16(base + 5120 + so,  Al + ga);
            cp16(base + 10240 + so, Bh + gb);
        }
    };

    const int w = tid >> 5, l = tid & 31;
    const int wm = (w >> 2) * 64;
    const int wn = (w & 3) * 32;
    const int qr = l >> 2;
    const int qc = (l & 3) * 2;
    const int arow = (l & 7) + ((l >> 3) & 1) * 8;
    const int acol = (l >> 4) * 8;
    const int brow = (l & 7) + ((l >> 4) & 1) * 8;
    const int bcol = ((l >> 3) & 1) * 8;

    float acc[4][4][4];
#pragma unroll
    for (int mi = 0; mi < 4; mi++)
#pragma unroll
        for (int ni = 0; ni < 4; ni++)
#pragma unroll
            for (int r = 0; r < 4; r++) acc[mi][ni][r] = 0.f;

    load_stage(0, 0);  CP_COMMIT();
    load_stage(1, 32); CP_COMMIT();

    for (int i = 0; i < T; i++) {
        if (i + 1 < T) CP_WAIT(1);
        else           CP_WAIT(0);
        __syncthreads();

        const __half* Ahs = sm + (i & 1) * 15360;
        const __half* Als = Ahs + 5120;
        const __half* Bhs = Ahs + 10240;

#pragma unroll
        for (int ks = 0; ks < 32; ks += 16) {
            unsigned ah[4][4], al[4][4];
#pragma unroll
            for (int mi = 0; mi < 4; mi++) {
                ldsm_x4(ah[mi], Ahs + (wm + mi * 16 + arow) * 40 + ks + acol);
                ldsm_x4(al[mi], Als + (wm + mi * 16 + arow) * 40 + ks + acol);
            }
#pragma unroll
            for (int p = 0; p < 2; p++) {
                unsigned bh[4];
                ldsm_x4(bh, Bhs + (wn + p * 16 + brow) * 40 + ks + bcol);
#pragma unroll
                for (int mi = 0; mi < 4; mi++) {
                    mma16816(acc[mi][2 * p],     ah[mi], bh);
                    mma16816(acc[mi][2 * p],     al[mi], bh);
                    mma16816(acc[mi][2 * p + 1], ah[mi], bh + 2);
                    mma16816(acc[mi][2 * p + 1], al[mi], bh + 2);
                }
            }
        }
        __syncthreads();
        if (i + 2 < T) {
            load_stage(i & 1, (i + 2) * 32);
            CP_COMMIT();
        }
    }

#pragma unroll
    for (int mi = 0; mi < 4; mi++) {
#pragma unroll
        for (int ni = 0; ni < 4; ni++) {
            int r  = bm + wm + mi * 16 + qr;
            int cc = bn + wn + ni * 8 + qc;
            float b0 = bias[cc], b1 = bias[cc + 1];
            float v0 = acc[mi][ni][0] + b0, v1 = acc[mi][ni][1] + b1;
            float v2 = acc[mi][ni][2] + b0, v3 = acc[mi][ni][3] + b1;
            if (mode == 0) {
                *(float2*)(Cf + (size_t)r * N + cc)       = make_float2(v0, v1);
                *(float2*)(Cf + (size_t)(r + 8) * N + cc) = make_float2(v2, v3);
            } else if (cc < 2048) {             // Q: split hi/lo, row-major
                unsigned h0, l0, h1, l1;
                split2h(v0, v1, h0, l0);
                split2h(v2, v3, h1, l1);
                *(unsigned*)(Qh + (size_t)r * DM + cc)       = h0;
                *(unsigned*)(Ql + (size_t)r * DM + cc)       = l0;
                *(unsigned*)(Qh + (size_t)(r + 8) * DM + cc) = h1;
                *(unsigned*)(Ql + (size_t)(r + 8) * DM + cc) = l1;
            } else if (cc < 2560) {             // K: hi only, row-major [M][512]
                int col = cc - 2048;
                __half2 h01 = __floats2half2_rn(v0, v1);
                __half2 h23 = __floats2half2_rn(v2, v3);
                *(__half2*)(Kh + (size_t)r * KVW + col)       = h01;
                *(__half2*)(Kh + (size_t)(r + 8) * KVW + col) = h23;
            } else {                            // V: hi only, transposed [b][dk][s]
                int col = cc - 2560;
                int bb = r >> 11, sl = r & (S_LEN - 1);
                size_t base = ((size_t)bb * KVW + col) * S_LEN;
                Vth[base + sl]               = __float2half_rn(v0);
                Vth[base + S_LEN + sl]       = __float2half_rn(v1);
                Vth[base + sl + 8]           = __float2half_rn(v2);
                Vth[base + S_LEN + sl + 8]   = __float2half_rn(v3);
            }
        }
    }
}

// ---------------------------------------------------------------------------
// fp16x2 flash attention (causal, GQA).
// smem halves: Qh[128x72]@0, Ql@9216 | 2 stages of {Kh,Vth}[64x72] @18432
// ---------------------------------------------------------------------------
#define FL_SMEM ((18432 + 2 * 9216) * 2)   // 73728 bytes

__global__ __launch_bounds__(256) void gqa_flash_fp16(
    const __half* __restrict__ Qh_g, const __half* __restrict__ Ql_g,
    const __half* __restrict__ Kh_g, const __half* __restrict__ Vth_g,
    __half* __restrict__ Ch_g, __half* __restrict__ Cl_g)
{
    extern __shared__ __half sb[];
    const int tid = threadIdx.x;
    const int w = tid >> 5, l = tid & 31;
    const int qr = l >> 2, qc = (l & 3) * 2;
    const int arow = (l & 7) + ((l >> 3) & 1) * 8;
    const int acol = (l >> 4) * 8;
    const int brow = (l & 7) + ((l >> 4) & 1) * 8;
    const int bcol = ((l >> 3) & 1) * 8;
    const int mtile = blockIdx.x, h = blockIdx.y, b = blockIdx.z;
    const int kvh = h >> 2;
    const int m0 = mtile * 128;
    const int kvTiles = 2 * mtile + 2;
    const int lastTile = 2 * mtile + (w >> 2);

    const __half* Qph = Qh_g + ((size_t)(b * S_LEN + m0)) * DM + h * 64;
    const __half* Qpl = Ql_g + ((size_t)(b * S_LEN + m0)) * DM + h * 64;
#pragma unroll
    for (int t = 0; t < 4; t++) {
        int idx = tid + t * 256;
        int row = idx >> 3, seg = (idx & 7) * 8;
        cp16(sb + row * 72 + seg,        Qph + (size_t)row * DM + seg);
        cp16(sb + 9216 + row * 72 + seg, Qpl + (size_t)row * DM + seg);
    }

    auto load_kv = [&](int sidx, int jt) {
        __half* st = sb + 18432 + sidx * 9216;
        const int k0 = jt * 64;
        const __half* Kg = Kh_g + ((size_t)(b * S_LEN + k0)) * KVW + kvh * 64;
        const __half* Vg = Vth_g + ((size_t)b * KVW + kvh * 64) * S_LEN + k0;
#pragma unroll
        for (int t = 0; t < 2; t++) {
            int idx = tid + t * 256;
            int row = idx >> 3, seg = (idx & 7) * 8;
            cp16(st + row * 72 + seg,        Kg + (size_t)row * KVW + seg);
            cp16(st + 4608 + row * 72 + seg, Vg + (size_t)row * S_LEN + seg);
        }
    };

    load_kv(0, 0); CP_COMMIT();
    load_kv(1, 1); CP_COMMIT();
    CP_WAIT(1);
    __syncthreads();

    unsigned aqh[4][4], aql[4][4];
#pragma unroll
    for (int j = 0; j < 4; j++) {
        ldsm_x4(aqh[j], sb + (w * 16 + arow) * 72 + j * 16 + acol);
        ldsm_x4(aql[j], sb + 9216 + (w * 16 + arow) * 72 + j * 16 + acol);
    }

    float o[8][4];
#pragma unroll
    for (int n = 0; n < 8; n++)
#pragma unroll
        for (int r = 0; r < 4; r++) o[n][r] = 0.f;
    float mrow0 = -INFINITY, mrow1 = -INFINITY, lrow0 = 0.f, lrow1 = 0.f;

    const int r0 = m0 + w * 16 + qr;
    const int r1 = r0 + 8;

    for (int jt = 0; jt < kvTiles; jt++) {
        if (jt > 0) {
            if (jt + 1 < kvTiles) CP_WAIT(1); else CP_WAIT(0);
            __syncthreads();
        }
        const __half* st = sb + 18432 + (jt & 1) * 9216;

        if (jt <= lastTile) {
            const int k0 = jt * 64;
            float s[8][4];
#pragma unroll
            for (int n = 0; n < 8; n++)
#pragma unroll
                for (int r = 0; r < 4; r++) s[n][r] = 0.f;

            // S = (Qh+Ql) Kh^T
#pragma unroll
            for (int j = 0; j < 4; j++) {
#pragma unroll
                for (int p = 0; p < 4; p++) {
                    unsigned bh[4];
                    ldsm_x4(bh, st + (p * 16 + brow) * 72 + j * 16 + bcol);
                    mma16816(s[2 * p],     aqh[j], bh);
                    mma16816(s[2 * p],     aql[j], bh);
                    mma16816(s[2 * p + 1], aqh[j], bh + 2);
                    mma16816(s[2 * p + 1], aql[j], bh + 2);
                }
            }

            const float rs = 0.125f;
            if (k0 + 63 > m0 + w * 16) {
#pragma unroll
                for (int n = 0; n < 8; n++) {
                    int c0 = k0 + n * 8 + qc;
                    s[n][0] = (c0     > r0) ? -1e30f : s[n][0] * rs;
                    s[n][1] = (c0 + 1 > r0) ? -1e30f : s[n][1] * rs;
                    s[n][2] = (c0     > r1) ? -1e30f : s[n][2] * rs;
                    s[n][3] = (c0 + 1 > r1) ? -1e30f : s[n][3] * rs;
                }
            } else {
#pragma unroll
                for (int n = 0; n < 8; n++)
#pragma unroll
                    for (int r = 0; r < 4; r++) s[n][r] *= rs;
            }

            float mx0 = -1e30f, mx1 = -1e30f;
#pragma unroll
            for (int n = 0; n < 8; n++) {
                mx0 = fmaxf(mx0, fmaxf(s[n][0], s[n][1]));
                mx1 = fmaxf(mx1, fmaxf(s[n][2], s[n][3]));
            }
            mx0 = fmaxf(mx0, __shfl_xor_sync(0xffffffffu, mx0, 1));
            mx0 = fmaxf(mx0, __shfl_xor_sync(0xffffffffu, mx0, 2));
            mx1 = fmaxf(mx1, __shfl_xor_sync(0xffffffffu, mx1, 1));
            mx1 = fmaxf(mx1, __shfl_xor_sync(0xffffffffu, mx1, 2));
            float mn0 = fmaxf(mrow0, mx0), mn1 = fmaxf(mrow1, mx1);
            float cr0 = __expf(mrow0 - mn0), cr1 = __expf(mrow1 - mn1);
            float sum0 = 0.f, sum1 = 0.f;
#pragma unroll
            for (int n = 0; n < 8; n++) {
                s[n][0] = __expf(s[n][0] - mn0);
                s[n][1] = __expf(s[n][1] - mn0);
                s[n][2] = __expf(s[n][2] - mn1);
                s[n][3] = __expf(s[n][3] - mn1);
                sum0 += s[n][0] + s[n][1];
                sum1 += s[n][2] + s[n][3];
            }
            sum0 += __shfl_xor_sync(0xffffffffu, sum0, 1);
            sum0 += __shfl_xor_sync(0xffffffffu, sum0, 2);
            sum1 += __shfl_xor_sync(0xffffffffu, sum1, 1);
            sum1 += __shfl_xor_sync(0xffffffffu, sum1, 2);
            lrow0 = lrow0 * cr0 + sum0;
            lrow1 = lrow1 * cr1 + sum1;
            mrow0 = mn0; mrow1 = mn1;
#pragma unroll
            for (int n = 0; n < 8; n++) {
                o[n][0] *= cr0; o[n][1] *= cr0;
                o[n][2] *= cr1; o[n][3] *= cr1;
            }

            unsigned pah[4][4], pal[4][4];
#pragma unroll
            for (int j = 0; j < 4; j++) {
                split2h(s[2 * j][0],     s[2 * j][1],     pah[j][0], pal[j][0]);
                split2h(s[2 * j][2],     s[2 * j][3],     pah[j][1], pal[j][1]);
                split2h(s[2 * j + 1][0], s[2 * j + 1][1], pah[j][2], pal[j][2]);
                split2h(s[2 * j + 1][2], s[2 * j + 1][3], pah[j][3], pal[j][3]);
            }

            // O += (Ph+Pl) Vh
#pragma unroll
            for (int j = 0; j < 4; j++) {
#pragma unroll
                for (int p = 0; p < 4; p++) {
                    unsigned bh[4];
                    ldsm_x4(bh, st + 4608 + (p * 16 + brow) * 72 + j * 16 + bcol);
                    mma16816(o[2 * p],     pah[j], bh);
                    mma16816(o[2 * p],     pal[j], bh);
                    mma16816(o[2 * p + 1], pah[j], bh + 2);
                    mma16816(o[2 * p + 1], pal[j], bh + 2);
                }
            }
        }

        __syncthreads();
        if (jt + 2 < kvTiles) {
            load_kv(jt & 1, jt + 2);
            CP_COMMIT();
        }
    }

    float inv0 = 1.f / lrow0, inv1 = 1.f / lrow1;
    size_t base0 = ((size_t)(b * S_LEN) + r0) * DM + h * 64;
    size_t base1 = ((size_t)(b * S_LEN) + r1) * DM + h * 64;
#pragma unroll
    for (int n = 0; n < 8; n++) {
        unsigned hh, ll;
        split2h(o[n][0] * inv0, o[n][1] * inv0, hh, ll);
        *(unsigned*)(Ch_g + base0 + n * 8 + qc) = hh;
        *(unsigned*)(Cl_g + base0 + n * 8 + qc) = ll;
        split2h(o[n][2] * inv1, o[n][3] * inv1, hh, ll);
        *(unsigned*)(Ch_g + base1 + n * 8 + qc) = hh;
        *(unsigned*)(Cl_g + base1 + n * 8 + qc) = ll;
    }
}

// ---------------------------------------------------------------------------
extern "C" void kernel_launch(void* const* d_in, const int* in_sizes, int n_in,
                              void* d_out, int out_size)
{
    (void)in_sizes; (void)n_in; (void)out_size;
    const float* x  = (const float*)d_in[0];
    const float* Wq = (const float*)d_in[2];
    const float* bq = (const float*)d_in[3];
    const float* Wk = (const float*)d_in[4];
    const float* bk = (const float*)d_in[5];
    const float* Wv = (const float*)d_in[6];
    const float* bv = (const float*)d_in[7];
    const float* Wo = (const float*)d_in[8];
    const float* bo = (const float*)d_in[9];
    float* out = (float*)d_out;

    __half *xh, *xl, *Qh, *Ql, *Kh, *Vth, *Ch, *Cl, *Wcat, *Woh;
    float* bcat;
    cudaGetSymbolAddress((void**)&xh, g_xh);     cudaGetSymbolAddress((void**)&xl, g_xl);
    cudaGetSymbolAddress((void**)&Qh, g_Qh);     cudaGetSymbolAddress((void**)&Ql, g_Ql);
    cudaGetSymbolAddress((void**)&Kh, g_Kh);     cudaGetSymbolAddress((void**)&Vth, g_Vth);
    cudaGetSymbolAddress((void**)&Ch, g_Ch);     cudaGetSymbolAddress((void**)&Cl, g_Cl);
    cudaGetSymbolAddress((void**)&Wcat, g_Wcat); cudaGetSymbolAddress((void**)&Woh, g_Woh);
    cudaGetSymbolAddress((void**)&bcat, g_bcat);

    cudaFuncSetAttribute(gemm_fp16x2,
                         cudaFuncAttributeMaxDynamicSharedMemorySize, GEMM_SMEM);
    cudaFuncSetAttribute(gqa_flash_fp16,
                         cudaFuncAttributeMaxDynamicSharedMemorySize, FL_SMEM);

    const int NX = MROWS * DM;

    // prep
    split_kernel<<<NX / 4 / 256, 256>>>(x, xh, xl, NX);
    transpose_half<<<dim3(DM / 32,  DM / 32), dim3(32, 8)>>>(Wq, Wcat, DM, DM);
    transpose_half<<<dim3(KVW / 32, DM / 32), dim3(32, 8)>>>(Wk, Wcat + 2048 * DM, DM, KVW);
    transpose_half<<<dim3(KVW / 32, DM / 32), dim3(32, 8)>>>(Wv, Wcat + 2560 * DM, DM, KVW);
    transpose_half<<<dim3(DM / 32,  DM / 32), dim3(32, 8)>>>(Wo, Woh, DM, DM);
    bias_concat<<<NCAT / 256, 256>>>(bq, bk, bv, bcat);

    // fused QKV projection (column-routed epilogue)
    gemm_fp16x2<<<dim3(NCAT / 128, MROWS / 128), 256, GEMM_SMEM>>>(
        xh, xl, Wcat, bcat, nullptr, Qh, Ql, Kh, Vth, 1, NCAT, DM);

    // attention
    gqa_flash_fp16<<<dim3(S_LEN / 128, NH, B_SZ), 256, FL_SMEM>>>(
        Qh, Ql, Kh, Vth, Ch, Cl);

    // output projection (fp32 out)
    gemm_fp16x2<<<dim3(DM / 128, MROWS / 128), 256, GEMM_SMEM>>>(
        Ch, Cl, Woh, bo, out, nullptr, nullptr, nullptr, nullptr, 0, DM, DM);
}

// round 11
// speedup vs baseline: 5.6201x; 1.3916x over previous
#include <cuda_runtime.h>
#include <cuda_fp16.h>
#include <cstdint>
#include <math.h>

#define B_SZ   2
#define S_LEN  2048
#define DM     2048
#define NH     32
#define NKV    8
#define DK     64
#define KVW    (NKV * DK)      // 512
#define MROWS  (B_SZ * S_LEN)  // 4096
#define NCAT   3072            // Q(2048) + K(512) + V(512)

// ---------------- scratch ----------------
__device__ __half g_xh[MROWS * DM];
__device__ __half g_Qh[MROWS * DM], g_Ql[MROWS * DM];
__device__ __half g_Kh[MROWS * KVW];
__device__ __half g_Vth[B_SZ * KVW * S_LEN];      // [b][dk][s]
__device__ __half g_Ch[MROWS * DM];
__device__ __half g_Wcat[NCAT * DM];              // [N][K] concat Q|K|V weights (hi)
__device__ __half g_Woh[DM * DM];
__device__ float  g_bcat[NCAT];

// ---------------- helpers ----------------
__device__ __forceinline__ void cp16(void* s, const void* g) {
    unsigned sa = (unsigned)__cvta_generic_to_shared(s);
    asm volatile("cp.async.cg.shared.global [%0], [%1], 16;\n" :: "r"(sa), "l"(g));
}
#define CP_COMMIT() asm volatile("cp.async.commit_group;\n")
#define CP_WAIT(n)  asm volatile("cp.async.wait_group %0;\n" :: "n"(n) : "memory")

__device__ __forceinline__ void mma16816(float* c, const unsigned* a, const unsigned* b) {
    asm volatile(
        "mma.sync.aligned.m16n8k16.row.col.f32.f16.f16.f32 "
        "{%0,%1,%2,%3}, {%4,%5,%6,%7}, {%8,%9}, {%0,%1,%2,%3};\n"
        : "+f"(c[0]), "+f"(c[1]), "+f"(c[2]), "+f"(c[3])
        : "r"(a[0]), "r"(a[1]), "r"(a[2]), "r"(a[3]), "r"(b[0]), "r"(b[1]));
}
__device__ __forceinline__ void ldsm_x4(unsigned* r, const void* p) {
    unsigned a = (unsigned)__cvta_generic_to_shared(p);
    asm volatile("ldmatrix.sync.aligned.m8n8.x4.shared.b16 {%0,%1,%2,%3}, [%4];\n"
                 : "=r"(r[0]), "=r"(r[1]), "=r"(r[2]), "=r"(r[3]) : "r"(a));
}
__device__ __forceinline__ void split2h(float v0, float v1, unsigned& hi, unsigned& lo) {
    __half2 h = __floats2half2_rn(v0, v1);
    __half2 l = __floats2half2_rn(v0 - __low2float(h), v1 - __high2float(h));
    hi = *(unsigned*)&h;
    lo = *(unsigned*)&l;
}

// ---------------- prep kernels ----------------
__global__ void conv_half(const float* __restrict__ s, __half* __restrict__ h, int n)
{
    int i = (blockIdx.x * blockDim.x + threadIdx.x) * 4;
    if (i >= n) return;
    float4 v = *(const float4*)(s + i);
    __half2 a = __floats2half2_rn(v.x, v.y);
    __half2 b = __floats2half2_rn(v.z, v.w);
    *(__half2*)(h + i)     = a;
    *(__half2*)(h + i + 2) = b;
}

// W [K][N] fp32 -> T [N][K] fp16 (hi only)
__global__ void transpose_half(const float* __restrict__ W, __half* __restrict__ T,
                               int K, int N)
{
    __shared__ float t[32][33];
    int bx = blockIdx.x * 32, by = blockIdx.y * 32;
    int tx = threadIdx.x, ty = threadIdx.y;
#pragma unroll
    for (int i = 0; i < 32; i += 8)
        t[ty + i][tx] = W[(size_t)(by + ty + i) * N + bx + tx];
    __syncthreads();
#pragma unroll
    for (int i = 0; i < 32; i += 8)
        T[(size_t)(bx + ty + i) * K + by + tx] = __float2half_rn(t[tx][ty + i]);
}

__global__ void bias_concat(const float* __restrict__ bq, const float* __restrict__ bk,
                            const float* __restrict__ bv, float* __restrict__ bc)
{
    int i = blockIdx.x * blockDim.x + threadIdx.x;
    if (i < 2048)      bc[i] = bq[i];
    else if (i < 2560) bc[i] = bk[i - 2048];
    else if (i < 3072) bc[i] = bv[i - 2560];
}

// ---------------------------------------------------------------------------
// fp16 tensor-core GEMM: C = Ah[M,K] @ Bh^T[N,K] + bias
// 128x128x32 tiles, 8 warps, ldmatrix feed, 2-stage cp.async.
// mode 0: fp32 out (O projection). mode 1: fused QKV routing by column.
// smem/stage: Ah,Bh = 2 x 128x40 halves = 20480B; 2 stages = 40960B
// ---------------------------------------------------------------------------
#define GEMM_SMEM 40960

__global__ __launch_bounds__(256) void gemm_fp16(
    const __half* __restrict__ Ah, const __half* __restrict__ Bh,
    const float* __restrict__ bias, float* __restrict__ Cf,
    __half* __restrict__ Qh, __half* __restrict__ Ql,
    __half* __restrict__ Kh, __half* __restrict__ Vth,
    int mode, int N, int K)
{
    extern __shared__ __half sm[];
    const int tid = threadIdx.x;
    const int bm = blockIdx.y * 128;
    const int bn = blockIdx.x * 128;
    const int T = K >> 5;

    auto load_stage = [&](int s, int k0) {
        __half* base = sm + s * 10240;
#pragma unroll
        for (int t = 0; t < 2; t++) {
            int c = tid + t * 256;
            int row = c >> 2;
            int seg = (c & 3) << 3;
            size_t ga = (size_t)(bm + row) * K + k0 + seg;
            size_t gb = (size_t)(bn + row) * K + k0 + seg;
            int so = row * 40 + seg;
            cp16(base + so,        Ah + ga);
            cp16(base + 5120 + so, Bh + gb);
        }
    };

    const int w = tid >> 5, l = tid & 31;
    const int wm = (w >> 2) * 64;
    const int wn = (w & 3) * 32;
    const int qr = l >> 2;
    const int qc = (l & 3) * 2;
    const int arow = (l & 7) + ((l >> 3) & 1) * 8;
    const int acol = (l >> 4) * 8;
    const int brow = (l & 7) + ((l >> 4) & 1) * 8;
    const int bcol = ((l >> 3) & 1) * 8;

    float acc[4][4][4];
#pragma unroll
    for (int mi = 0; mi < 4; mi++)
#pragma unroll
        for (int ni = 0; ni < 4; ni++)
#pragma unroll
            for (int r = 0; r < 4; r++) acc[mi][ni][r] = 0.f;

    load_stage(0, 0);  CP_COMMIT();
    load_stage(1, 32); CP_COMMIT();

    for (int i = 0; i < T; i++) {
        if (i + 1 < T) CP_WAIT(1);
        else           CP_WAIT(0);
        __syncthreads();

        const __half* Ahs = sm + (i & 1) * 10240;
        const __half* Bhs = Ahs + 5120;

#pragma unroll
        for (int ks = 0; ks < 32; ks += 16) {
            unsigned ah[4][4];
#pragma unroll
            for (int mi = 0; mi < 4; mi++)
                ldsm_x4(ah[mi], Ahs + (wm + mi * 16 + arow) * 40 + ks + acol);
#pragma unroll
            for (int p = 0; p < 2; p++) {
                unsigned bh[4];
                ldsm_x4(bh, Bhs + (wn + p * 16 + brow) * 40 + ks + bcol);
#pragma unroll
                for (int mi = 0; mi < 4; mi++) {
                    mma16816(acc[mi][2 * p],     ah[mi], bh);
                    mma16816(acc[mi][2 * p + 1], ah[mi], bh + 2);
                }
            }
        }
        __syncthreads();
        if (i + 2 < T) {
            load_stage(i & 1, (i + 2) * 32);
            CP_COMMIT();
        }
    }

#pragma unroll
    for (int mi = 0; mi < 4; mi++) {
#pragma unroll
        for (int ni = 0; ni < 4; ni++) {
            int r  = bm + wm + mi * 16 + qr;
            int cc = bn + wn + ni * 8 + qc;
            float b0 = bias[cc], b1 = bias[cc + 1];
            float v0 = acc[mi][ni][0] + b0, v1 = acc[mi][ni][1] + b1;
            float v2 = acc[mi][ni][2] + b0, v3 = acc[mi][ni][3] + b1;
            if (mode == 0) {
                *(float2*)(Cf + (size_t)r * N + cc)       = make_float2(v0, v1);
                *(float2*)(Cf + (size_t)(r + 8) * N + cc) = make_float2(v2, v3);
            } else if (cc < 2048) {             // Q: split hi/lo (attention keeps lo)
                unsigned h0, l0, h1, l1;
                split2h(v0, v1, h0, l0);
                split2h(v2, v3, h1, l1);
                *(unsigned*)(Qh + (size_t)r * DM + cc)       = h0;
                *(unsigned*)(Ql + (size_t)r * DM + cc)       = l0;
                *(unsigned*)(Qh + (size_t)(r + 8) * DM + cc) = h1;
                *(unsigned*)(Ql + (size_t)(r + 8) * DM + cc) = l1;
            } else if (cc < 2560) {             // K: hi only, row-major [M][512]
                int col = cc - 2048;
                *(__half2*)(Kh + (size_t)r * KVW + col)       = __floats2half2_rn(v0, v1);
                *(__half2*)(Kh + (size_t)(r + 8) * KVW + col) = __floats2half2_rn(v2, v3);
            } else {                            // V: hi only, transposed [b][dk][s]
                int col = cc - 2560;
                int bb = r >> 11, sl = r & (S_LEN - 1);
                size_t base = ((size_t)bb * KVW + col) * S_LEN;
                Vth[base + sl]             = __float2half_rn(v0);
                Vth[base + S_LEN + sl]     = __float2half_rn(v1);
                Vth[base + sl + 8]         = __float2half_rn(v2);
                Vth[base + S_LEN + sl + 8] = __float2half_rn(v3);
            }
        }
    }
}

// ---------------------------------------------------------------------------
// fp16x2 flash attention (causal, GQA) — unchanged math from R10,
// epilogue stores context hi only.
// smem halves: Qh[128x72]@0, Ql@9216 | 2 stages of {Kh,Vth}[64x72] @18432
// ---------------------------------------------------------------------------
#define FL_SMEM ((18432 + 2 * 9216) * 2)   // 73728 bytes

__global__ __launch_bounds__(256) void gqa_flash_fp16(
    const __half* __restrict__ Qh_g, const __half* __restrict__ Ql_g,
    const __half* __restrict__ Kh_g, const __half* __restrict__ Vth_g,
    __half* __restrict__ Ch_g)
{
    extern __shared__ __half sb[];
    const int tid = threadIdx.x;
    const int w = tid >> 5, l = tid & 31;
    const int qr = l >> 2, qc = (l & 3) * 2;
    const int arow = (l & 7) + ((l >> 3) & 1) * 8;
    const int acol = (l >> 4) * 8;
    const int brow = (l & 7) + ((l >> 4) & 1) * 8;
    const int bcol = ((l >> 3) & 1) * 8;
    const int mtile = blockIdx.x, h = blockIdx.y, b = blockIdx.z;
    const int kvh = h >> 2;
    const int m0 = mtile * 128;
    const int kvTiles = 2 * mtile + 2;
    const int lastTile = 2 * mtile + (w >> 2);

    const __half* Qph = Qh_g + ((size_t)(b * S_LEN + m0)) * DM + h * 64;
    const __half* Qpl = Ql_g + ((size_t)(b * S_LEN + m0)) * DM + h * 64;
#pragma unroll
    for (int t = 0; t < 4; t++) {
        int idx = tid + t * 256;
        int row = idx >> 3, seg = (idx & 7) * 8;
        cp16(sb + row * 72 + seg,        Qph + (size_t)row * DM + seg);
        cp16(sb + 9216 + row * 72 + seg, Qpl + (size_t)row * DM + seg);
    }

    auto load_kv = [&](int sidx, int jt) {
        __half* st = sb + 18432 + sidx * 9216;
        const int k0 = jt * 64;
        const __half* Kg = Kh_g + ((size_t)(b * S_LEN + k0)) * KVW + kvh * 64;
        const __half* Vg = Vth_g + ((size_t)b * KVW + kvh * 64) * S_LEN + k0;
#pragma unroll
        for (int t = 0; t < 2; t++) {
            int idx = tid + t * 256;
            int row = idx >> 3, seg = (idx & 7) * 8;
            cp16(st + row * 72 + seg,        Kg + (size_t)row * KVW + seg);
            cp16(st + 4608 + row * 72 + seg, Vg + (size_t)row * S_LEN + seg);
        }
    };

    load_kv(0, 0); CP_COMMIT();
    load_kv(1, 1); CP_COMMIT();
    CP_WAIT(1);
    __syncthreads();

    unsigned aqh[4][4], aql[4][4];
#pragma unroll
    for (int j = 0; j < 4; j++) {
        ldsm_x4(aqh[j], sb + (w * 16 + arow) * 72 + j * 16 + acol);
        ldsm_x4(aql[j], sb + 9216 + (w * 16 + arow) * 72 + j * 16 + acol);
    }

    float o[8][4];
#pragma unroll
    for (int n = 0; n < 8; n++)
#pragma unroll
        for (int r = 0; r < 4; r++) o[n][r] = 0.f;
    float mrow0 = -INFINITY, mrow1 = -INFINITY, lrow0 = 0.f, lrow1 = 0.f;

    const int r0 = m0 + w * 16 + qr;
    const int r1 = r0 + 8;

    for (int jt = 0; jt < kvTiles; jt++) {
        if (jt > 0) {
            if (jt + 1 < kvTiles) CP_WAIT(1); else CP_WAIT(0);
            __syncthreads();
        }
        const __half* st = sb + 18432 + (jt & 1) * 9216;

        if (jt <= lastTile) {
            const int k0 = jt * 64;
            float s[8][4];
#pragma unroll
            for (int n = 0; n < 8; n++)
#pragma unroll
                for (int r = 0; r < 4; r++) s[n][r] = 0.f;

            // S = (Qh+Ql) Kh^T
#pragma unroll
            for (int j = 0; j < 4; j++) {
#pragma unroll
                for (int p = 0; p < 4; p++) {
                    unsigned bh[4];
                    ldsm_x4(bh, st + (p * 16 + brow) * 72 + j * 16 + bcol);
                    mma16816(s[2 * p],     aqh[j], bh);
                    mma16816(s[2 * p],     aql[j], bh);
                    mma16816(s[2 * p + 1], aqh[j], bh + 2);
                    mma16816(s[2 * p + 1], aql[j], bh + 2);
                }
            }

            const float rs = 0.125f;
            if (k0 + 63 > m0 + w * 16) {
#pragma unroll
                for (int n = 0; n < 8; n++) {
                    int c0 = k0 + n * 8 + qc;
                    s[n][0] = (c0     > r0) ? -1e30f : s[n][0] * rs;
                    s[n][1] = (c0 + 1 > r0) ? -1e30f : s[n][1] * rs;
                    s[n][2] = (c0     > r1) ? -1e30f : s[n][2] * rs;
                    s[n][3] = (c0 + 1 > r1) ? -1e30f : s[n][3] * rs;
                }
            } else {
#pragma unroll
                for (int n = 0; n < 8; n++)
#pragma unroll
                    for (int r = 0; r < 4; r++) s[n][r] *= rs;
            }

            float mx0 = -1e30f, mx1 = -1e30f;
#pragma unroll
            for (int n = 0; n < 8; n++) {
                mx0 = fmaxf(mx0, fmaxf(s[n][0], s[n][1]));
                mx1 = fmaxf(mx1, fmaxf(s[n][2], s[n][3]));
            }
            mx0 = fmaxf(mx0, __shfl_xor_sync(0xffffffffu, mx0, 1));
            mx0 = fmaxf(mx0, __shfl_xor_sync(0xffffffffu, mx0, 2));
            mx1 = fmaxf(mx1, __shfl_xor_sync(0xffffffffu, mx1, 1));
            mx1 = fmaxf(mx1, __shfl_xor_sync(0xffffffffu, mx1, 2));
            float mn0 = fmaxf(mrow0, mx0), mn1 = fmaxf(mrow1, mx1);
            float cr0 = __expf(mrow0 - mn0), cr1 = __expf(mrow1 - mn1);
            float sum0 = 0.f, sum1 = 0.f;
#pragma unroll
            for (int n = 0; n < 8; n++) {
                s[n][0] = __expf(s[n][0] - mn0);
                s[n][1] = __expf(s[n][1] - mn0);
                s[n][2] = __expf(s[n][2] - mn1);
                s[n][3] = __expf(s[n][3] - mn1);
                sum0 += s[n][0] + s[n][1];
                sum1 += s[n][2] + s[n][3];
            }
            sum0 += __shfl_xor_sync(0xffffffffu, sum0, 1);
            sum0 += __shfl_xor_sync(0xffffffffu, sum0, 2);
            sum1 += __shfl_xor_sync(0xffffffffu, sum1, 1);
            sum1 += __shfl_xor_sync(0xffffffffu, sum1, 2);
            lrow0 = lrow0 * cr0 + sum0;
            lrow1 = lrow1 * cr1 + sum1;
            mrow0 = mn0; mrow1 = mn1;
#pragma unroll
            for (int n = 0; n < 8; n++) {
                o[n][0] *= cr0; o[n][1] *= cr0;
                o[n][2] *= cr1; o[n][3] *= cr1;
            }

            unsigned pah[4][4], pal[4][4];
#pragma unroll
            for (int j = 0; j < 4; j++) {
                split2h(s[2 * j][0],     s[2 * j][1],     pah[j][0], pal[j][0]);
                split2h(s[2 * j][2],     s[2 * j][3],     pah[j][1], pal[j][1]);
                split2h(s[2 * j + 1][0], s[2 * j + 1][1], pah[j][2], pal[j][2]);
                split2h(s[2 * j + 1][2], s[2 * j + 1][3], pah[j][3], pal[j][3]);
            }

            // O += (Ph+Pl) Vh
#pragma unroll
            for (int j = 0; j < 4; j++) {
#pragma unroll
                for (int p = 0; p < 4; p++) {
                    unsigned bh[4];
                    ldsm_x4(bh, st + 4608 + (p * 16 + brow) * 72 + j * 16 + bcol);
                    mma16816(o[2 * p],     pah[j], bh);
                    mma16816(o[2 * p],     pal[j], bh);
                    mma16816(o[2 * p + 1], pah[j], bh + 2);
                    mma16816(o[2 * p + 1], pal[j], bh + 2);
                }
            }
        }

        __syncthreads();
        if (jt + 2 < kvTiles) {
            load_kv(jt & 1, jt + 2);
            CP_COMMIT();
        }
    }

    float inv0 = 1.f / lrow0, inv1 = 1.f / lrow1;
    size_t base0 = ((size_t)(b * S_LEN) + r0) * DM + h * 64;
    size_t base1 = ((size_t)(b * S_LEN) + r1) * DM + h * 64;
#pragma unroll
    for (int n = 0; n < 8; n++) {
        *(__half2*)(Ch_g + base0 + n * 8 + qc) = __floats2half2_rn(o[n][0] * inv0, o[n][1] * inv0);
        *(__half2*)(Ch_g + base1 + n * 8 + qc) = __floats2half2_rn(o[n][2] * inv1, o[n][3] * inv1);
    }
}

// ---------------------------------------------------------------------------
extern "C" void kernel_launch(void* const* d_in, const int* in_sizes, int n_in,
                              void* d_out, int out_size)
{
    (void)in_sizes; (void)n_in; (void)out_size;
    const float* x  = (const float*)d_in[0];
    const float* Wq = (const float*)d_in[2];
    const float* bq = (const float*)d_in[3];
    const float* Wk = (const float*)d_in[4];
    const float* bk = (const float*)d_in[5];
    const float* Wv = (const float*)d_in[6];
    const float* bv = (const float*)d_in[7];
    const float* Wo = (const float*)d_in[8];
    const float* bo = (const float*)d_in[9];
    float* out = (float*)d_out;

    __half *xh, *Qh, *Ql, *Kh, *Vth, *Ch, *Wcat, *Woh;
    float* bcat;
    cudaGetSymbolAddress((void**)&xh, g_xh);
    cudaGetSymbolAddress((void**)&Qh, g_Qh);     cudaGetSymbolAddress((void**)&Ql, g_Ql);
    cudaGetSymbolAddress((void**)&Kh, g_Kh);     cudaGetSymbolAddress((void**)&Vth, g_Vth);
    cudaGetSymbolAddress((void**)&Ch, g_Ch);
    cudaGetSymbolAddress((void**)&Wcat, g_Wcat); cudaGetSymbolAddress((void**)&Woh, g_Woh);
    cudaGetSymbolAddress((void**)&bcat, g_bcat);

    cudaFuncSetAttribute(gemm_fp16,
                         cudaFuncAttributeMaxDynamicSharedMemorySize, GEMM_SMEM);
    cudaFuncSetAttribute(gqa_flash_fp16,
                         cudaFuncAttributeMaxDynamicSharedMemorySize, FL_SMEM);

    const int NX = MROWS * DM;

    // prep
    conv_half<<<NX / 4 / 256, 256>>>(x, xh, NX);
    transpose_half<<<dim3(DM / 32,  DM / 32), dim3(32, 8)>>>(Wq, Wcat, DM, DM);
    transpose_half<<<dim3(KVW / 32, DM / 32), dim3(32, 8)>>>(Wk, Wcat + 2048 * DM, DM, KVW);
    transpose_half<<<dim3(KVW / 32, DM / 32), dim3(32, 8)>>>(Wv, Wcat + 2560 * DM, DM, KVW);
    transpose_half<<<dim3(DM / 32,  DM / 32), dim3(32, 8)>>>(Wo, Woh, DM, DM);
    bias_concat<<<NCAT / 256, 256>>>(bq, bk, bv, bcat);

    // fused QKV projection (column-routed epilogue)
    gemm_fp16<<<dim3(NCAT / 128, MROWS / 128), 256, GEMM_SMEM>>>(
        xh, Wcat, bcat, nullptr, Qh, Ql, Kh, Vth, 1, NCAT, DM);

    // attention
    gqa_flash_fp16<<<dim3(S_LEN / 128, NH, B_SZ), 256, FL_SMEM>>>(
        Qh, Ql, Kh, Vth, Ch);

    // output projection (fp32 out)
    gemm_fp16<<<dim3(DM / 128, MROWS / 128), 256, GEMM_SMEM>>>(
        Ch, Woh, bo, out, nullptr, nullptr, nullptr, nullptr, 0, DM, DM);
}

// round 12
// speedup vs baseline: 6.4133x; 1.1411x over previous
#include <cuda_runtime.h>
#include <cuda_fp16.h>
#include <cstdint>
#include <math.h>

#define B_SZ   2
#define S_LEN  2048
#define DM     2048
#define NH     32
#define NKV    8
#define DK     64
#define KVW    (NKV * DK)      // 512
#define MROWS  (B_SZ * S_LEN)  // 4096
#define NCAT   3072            // Q(2048) + K(512) + V(512)

// ---------------- scratch ----------------
__device__ __half g_xh[MROWS * DM];
__device__ __half g_Qh[MROWS * DM];
__device__ __half g_Kh[MROWS * KVW];
__device__ __half g_Vth[B_SZ * KVW * S_LEN];      // [b][dk][s]
__device__ __half g_Ch[MROWS * DM];
__device__ __half g_Wcat[NCAT * DM];              // [N][K] concat Q|K|V weights (hi)
__device__ __half g_Woh[DM * DM];
__device__ float  g_bcat[NCAT];

// ---------------- helpers ----------------
__device__ __forceinline__ void cp16(void* s, const void* g) {
    unsigned sa = (unsigned)__cvta_generic_to_shared(s);
    asm volatile("cp.async.cg.shared.global [%0], [%1], 16;\n" :: "r"(sa), "l"(g));
}
#define CP_COMMIT() asm volatile("cp.async.commit_group;\n")
#define CP_WAIT(n)  asm volatile("cp.async.wait_group %0;\n" :: "n"(n) : "memory")

__device__ __forceinline__ void mma16816(float* c, const unsigned* a, const unsigned* b) {
    asm volatile(
        "mma.sync.aligned.m16n8k16.row.col.f32.f16.f16.f32 "
        "{%0,%1,%2,%3}, {%4,%5,%6,%7}, {%8,%9}, {%0,%1,%2,%3};\n"
        : "+f"(c[0]), "+f"(c[1]), "+f"(c[2]), "+f"(c[3])
        : "r"(a[0]), "r"(a[1]), "r"(a[2]), "r"(a[3]), "r"(b[0]), "r"(b[1]));
}
__device__ __forceinline__ void ldsm_x4(unsigned* r, const void* p) {
    unsigned a = (unsigned)__cvta_generic_to_shared(p);
    asm volatile("ldmatrix.sync.aligned.m8n8.x4.shared.b16 {%0,%1,%2,%3}, [%4];\n"
                 : "=r"(r[0]), "=r"(r[1]), "=r"(r[2]), "=r"(r[3]) : "r"(a));
}
__device__ __forceinline__ unsigned pack2h(float v0, float v1) {
    __half2 h = __floats2half2_rn(v0, v1);
    return *(unsigned*)&h;
}

// ---------------- prep kernels ----------------
__global__ void conv_half(const float* __restrict__ s, __half* __restrict__ h, int n)
{
    int i = (blockIdx.x * blockDim.x + threadIdx.x) * 4;
    if (i >= n) return;
    float4 v = *(const float4*)(s + i);
    *(__half2*)(h + i)     = __floats2half2_rn(v.x, v.y);
    *(__half2*)(h + i + 2) = __floats2half2_rn(v.z, v.w);
}

// W [K][N] fp32 -> T [N][K] fp16 (hi only)
__global__ void transpose_half(const float* __restrict__ W, __half* __restrict__ T,
                               int K, int N)
{
    __shared__ float t[32][33];
    int bx = blockIdx.x * 32, by = blockIdx.y * 32;
    int tx = threadIdx.x, ty = threadIdx.y;
#pragma unroll
    for (int i = 0; i < 32; i += 8)
        t[ty + i][tx] = W[(size_t)(by + ty + i) * N + bx + tx];
    __syncthreads();
#pragma unroll
    for (int i = 0; i < 32; i += 8)
        T[(size_t)(bx + ty + i) * K + by + tx] = __float2half_rn(t[tx][ty + i]);
}

__global__ void bias_concat(const float* __restrict__ bq, const float* __restrict__ bk,
                            const float* __restrict__ bv, float* __restrict__ bc)
{
    int i = blockIdx.x * blockDim.x + threadIdx.x;
    if (i < 2048)      bc[i] = bq[i];
    else if (i < 2560) bc[i] = bk[i - 2048];
    else if (i < 3072) bc[i] = bv[i - 2560];
}

// ---------------------------------------------------------------------------
// fp16 tensor-core GEMM: C = Ah[M,K] @ Bh^T[N,K] + bias
// 128x128x32 tiles, 8 warps, ldmatrix feed, 2-stage cp.async.
// mode 0: fp32 out (O projection). mode 1: fused QKV routing by column.
// ---------------------------------------------------------------------------
#define GEMM_SMEM 40960

__global__ __launch_bounds__(256) void gemm_fp16(
    const __half* __restrict__ Ah, const __half* __restrict__ Bh,
    const float* __restrict__ bias, float* __restrict__ Cf,
    __half* __restrict__ Qh, __half* __restrict__ Kh, __half* __restrict__ Vth,
    int mode, int N, int K)
{
    extern __shared__ __half sm[];
    const int tid = threadIdx.x;
    const int bm = blockIdx.y * 128;
    const int bn = blockIdx.x * 128;
    const int T = K >> 5;

    auto load_stage = [&](int s, int k0) {
        __half* base = sm + s * 10240;
#pragma unroll
        for (int t = 0; t < 2; t++) {
            int c = tid + t * 256;
            int row = c >> 2;
            int seg = (c & 3) << 3;
            size_t ga = (size_t)(bm + row) * K + k0 + seg;
            size_t gb = (size_t)(bn + row) * K + k0 + seg;
            int so = row * 40 + seg;
            cp16(base + so,        Ah + ga);
            cp16(base + 5120 + so, Bh + gb);
        }
    };

    const int w = tid >> 5, l = tid & 31;
    const int wm = (w >> 2) * 64;
    const int wn = (w & 3) * 32;
    const int qr = l >> 2;
    const int qc = (l & 3) * 2;
    const int arow = (l & 7) + ((l >> 3) & 1) * 8;
    const int acol = (l >> 4) * 8;
    const int brow = (l & 7) + ((l >> 4) & 1) * 8;
    const int bcol = ((l >> 3) & 1) * 8;

    float acc[4][4][4];
#pragma unroll
    for (int mi = 0; mi < 4; mi++)
#pragma unroll
        for (int ni = 0; ni < 4; ni++)
#pragma unroll
            for (int r = 0; r < 4; r++) acc[mi][ni][r] = 0.f;

    load_stage(0, 0);  CP_COMMIT();
    load_stage(1, 32); CP_COMMIT();

    for (int i = 0; i < T; i++) {
        if (i + 1 < T) CP_WAIT(1);
        else           CP_WAIT(0);
        __syncthreads();

        const __half* Ahs = sm + (i & 1) * 10240;
        const __half* Bhs = Ahs + 5120;

#pragma unroll
        for (int ks = 0; ks < 32; ks += 16) {
            unsigned ah[4][4];
#pragma unroll
            for (int mi = 0; mi < 4; mi++)
                ldsm_x4(ah[mi], Ahs + (wm + mi * 16 + arow) * 40 + ks + acol);
#pragma unroll
            for (int p = 0; p < 2; p++) {
                unsigned bh[4];
                ldsm_x4(bh, Bhs + (wn + p * 16 + brow) * 40 + ks + bcol);
#pragma unroll
                for (int mi = 0; mi < 4; mi++) {
                    mma16816(acc[mi][2 * p],     ah[mi], bh);
                    mma16816(acc[mi][2 * p + 1], ah[mi], bh + 2);
                }
            }
        }
        __syncthreads();
        if (i + 2 < T) {
            load_stage(i & 1, (i + 2) * 32);
            CP_COMMIT();
        }
    }

#pragma unroll
    for (int mi = 0; mi < 4; mi++) {
#pragma unroll
        for (int ni = 0; ni < 4; ni++) {
            int r  = bm + wm + mi * 16 + qr;
            int cc = bn + wn + ni * 8 + qc;
            float b0 = bias[cc], b1 = bias[cc + 1];
            float v0 = acc[mi][ni][0] + b0, v1 = acc[mi][ni][1] + b1;
            float v2 = acc[mi][ni][2] + b0, v3 = acc[mi][ni][3] + b1;
            if (mode == 0) {
                *(float2*)(Cf + (size_t)r * N + cc)       = make_float2(v0, v1);
                *(float2*)(Cf + (size_t)(r + 8) * N + cc) = make_float2(v2, v3);
            } else if (cc < 2048) {             // Q: hi only, row-major
                *(unsigned*)(Qh + (size_t)r * DM + cc)       = pack2h(v0, v1);
                *(unsigned*)(Qh + (size_t)(r + 8) * DM + cc) = pack2h(v2, v3);
            } else if (cc < 2560) {             // K: hi only, row-major [M][512]
                int col = cc - 2048;
                *(unsigned*)(Kh + (size_t)r * KVW + col)       = pack2h(v0, v1);
                *(unsigned*)(Kh + (size_t)(r + 8) * KVW + col) = pack2h(v2, v3);
            } else {                            // V: hi only, transposed [b][dk][s]
                int col = cc - 2560;
                int bb = r >> 11, sl = r & (S_LEN - 1);
                size_t base = ((size_t)bb * KVW + col) * S_LEN;
                Vth[base + sl]             = __float2half_rn(v0);
                Vth[base + S_LEN + sl]     = __float2half_rn(v1);
                Vth[base + sl + 8]         = __float2half_rn(v2);
                Vth[base + S_LEN + sl + 8] = __float2half_rn(v3);
            }
        }
    }
}

// ---------------------------------------------------------------------------
// fp16 flash attention (causal, GQA), hi-only Q/K/V/P.
// smem halves: Qh[128x72]@0 | 2 stages of {Kh,Vth}[64x72] @9216
// ---------------------------------------------------------------------------
#define FL_SMEM ((9216 + 2 * 9216) * 2)   // 55296 bytes

__global__ __launch_bounds__(256) void gqa_flash_fp16(
    const __half* __restrict__ Qh_g, const __half* __restrict__ Kh_g,
    const __half* __restrict__ Vth_g, __half* __restrict__ Ch_g)
{
    extern __shared__ __half sb[];
    const int tid = threadIdx.x;
    const int w = tid >> 5, l = tid & 31;
    const int qr = l >> 2, qc = (l & 3) * 2;
    const int arow = (l & 7) + ((l >> 3) & 1) * 8;
    const int acol = (l >> 4) * 8;
    const int brow = (l & 7) + ((l >> 4) & 1) * 8;
    const int bcol = ((l >> 3) & 1) * 8;
    const int mtile = blockIdx.x, h = blockIdx.y, b = blockIdx.z;
    const int kvh = h >> 2;
    const int m0 = mtile * 128;
    const int kvTiles = 2 * mtile + 2;
    const int lastTile = 2 * mtile + (w >> 2);

    const __half* Qph = Qh_g + ((size_t)(b * S_LEN + m0)) * DM + h * 64;
#pragma unroll
    for (int t = 0; t < 4; t++) {
        int idx = tid + t * 256;
        int row = idx >> 3, seg = (idx & 7) * 8;
        cp16(sb + row * 72 + seg, Qph + (size_t)row * DM + seg);
    }

    auto load_kv = [&](int sidx, int jt) {
        __half* st = sb + 9216 + sidx * 9216;
        const int k0 = jt * 64;
        const __half* Kg = Kh_g + ((size_t)(b * S_LEN + k0)) * KVW + kvh * 64;
        const __half* Vg = Vth_g + ((size_t)b * KVW + kvh * 64) * S_LEN + k0;
#pragma unroll
        for (int t = 0; t < 2; t++) {
            int idx = tid + t * 256;
            int row = idx >> 3, seg = (idx & 7) * 8;
            cp16(st + row * 72 + seg,        Kg + (size_t)row * KVW + seg);
            cp16(st + 4608 + row * 72 + seg, Vg + (size_t)row * S_LEN + seg);
        }
    };

    load_kv(0, 0); CP_COMMIT();
    load_kv(1, 1); CP_COMMIT();
    CP_WAIT(1);
    __syncthreads();

    unsigned aqh[4][4];
#pragma unroll
    for (int j = 0; j < 4; j++)
        ldsm_x4(aqh[j], sb + (w * 16 + arow) * 72 + j * 16 + acol);

    float o[8][4];
#pragma unroll
    for (int n = 0; n < 8; n++)
#pragma unroll
        for (int r = 0; r < 4; r++) o[n][r] = 0.f;
    float mrow0 = -INFINITY, mrow1 = -INFINITY, lrow0 = 0.f, lrow1 = 0.f;

    const int r0 = m0 + w * 16 + qr;
    const int r1 = r0 + 8;

    for (int jt = 0; jt < kvTiles; jt++) {
        if (jt > 0) {
            if (jt + 1 < kvTiles) CP_WAIT(1); else CP_WAIT(0);
            __syncthreads();
        }
        const __half* st = sb + 9216 + (jt & 1) * 9216;

        if (jt <= lastTile) {
            const int k0 = jt * 64;
            float s[8][4];
#pragma unroll
            for (int n = 0; n < 8; n++)
#pragma unroll
                for (int r = 0; r < 4; r++) s[n][r] = 0.f;

            // S = Qh Kh^T
#pragma unroll
            for (int j = 0; j < 4; j++) {
#pragma unroll
                for (int p = 0; p < 4; p++) {
                    unsigned bh[4];
                    ldsm_x4(bh, st + (p * 16 + brow) * 72 + j * 16 + bcol);
                    mma16816(s[2 * p],     aqh[j], bh);
                    mma16816(s[2 * p + 1], aqh[j], bh + 2);
                }
            }

            const float rs = 0.125f;
            if (k0 + 63 > m0 + w * 16) {
#pragma unroll
                for (int n = 0; n < 8; n++) {
                    int c0 = k0 + n * 8 + qc;
                    s[n][0] = (c0     > r0) ? -1e30f : s[n][0] * rs;
                    s[n][1] = (c0 + 1 > r0) ? -1e30f : s[n][1] * rs;
                    s[n][2] = (c0     > r1) ? -1e30f : s[n][2] * rs;
                    s[n][3] = (c0 + 1 > r1) ? -1e30f : s[n][3] * rs;
                }
            } else {
#pragma unroll
                for (int n = 0; n < 8; n++)
#pragma unroll
                    for (int r = 0; r < 4; r++) s[n][r] *= rs;
            }

            float mx0 = -1e30f, mx1 = -1e30f;
#pragma unroll
            for (int n = 0; n < 8; n++) {
                mx0 = fmaxf(mx0, fmaxf(s[n][0], s[n][1]));
                mx1 = fmaxf(mx1, fmaxf(s[n][2], s[n][3]));
            }
            mx0 = fmaxf(mx0, __shfl_xor_sync(0xffffffffu, mx0, 1));
            mx0 = fmaxf(mx0, __shfl_xor_sync(0xffffffffu, mx0, 2));
            mx1 = fmaxf(mx1, __shfl_xor_sync(0xffffffffu, mx1, 1));
            mx1 = fmaxf(mx1, __shfl_xor_sync(0xffffffffu, mx1, 2));
            float mn0 = fmaxf(mrow0, mx0), mn1 = fmaxf(mrow1, mx1);
            float cr0 = __expf(mrow0 - mn0), cr1 = __expf(mrow1 - mn1);
            float sum0 = 0.f, sum1 = 0.f;
#pragma unroll
            for (int n = 0; n < 8; n++) {
                s[n][0] = __expf(s[n][0] - mn0);
                s[n][1] = __expf(s[n][1] - mn0);
                s[n][2] = __expf(s[n][2] - mn1);
                s[n][3] = __expf(s[n][3] - mn1);
                sum0 += s[n][0] + s[n][1];
                sum1 += s[n][2] + s[n][3];
            }
            sum0 += __shfl_xor_sync(0xffffffffu, sum0, 1);
            sum0 += __shfl_xor_sync(0xffffffffu, sum0, 2);
            sum1 += __shfl_xor_sync(0xffffffffu, sum1, 1);
            sum1 += __shfl_xor_sync(0xffffffffu, sum1, 2);
            lrow0 = lrow0 * cr0 + sum0;
            lrow1 = lrow1 * cr1 + sum1;
            mrow0 = mn0; mrow1 = mn1;
#pragma unroll
            for (int n = 0; n < 8; n++) {
                o[n][0] *= cr0; o[n][1] *= cr0;
                o[n][2] *= cr1; o[n][3] *= cr1;
            }

            // P fragments (hi only)
            unsigned pah[4][4];
#pragma unroll
            for (int j = 0; j < 4; j++) {
                pah[j][0] = pack2h(s[2 * j][0],     s[2 * j][1]);
                pah[j][1] = pack2h(s[2 * j][2],     s[2 * j][3]);
                pah[j][2] = pack2h(s[2 * j + 1][0], s[2 * j + 1][1]);
                pah[j][3] = pack2h(s[2 * j + 1][2], s[2 * j + 1][3]);
            }

            // O += Ph Vh
#pragma unroll
            for (int j = 0; j < 4; j++) {
#pragma unroll
                for (int p = 0; p < 4; p++) {
                    unsigned bh[4];
                    ldsm_x4(bh, st + 4608 + (p * 16 + brow) * 72 + j * 16 + bcol);
                    mma16816(o[2 * p],     pah[j], bh);
                    mma16816(o[2 * p + 1], pah[j], bh + 2);
                }
            }
        }

        __syncthreads();
        if (jt + 2 < kvTiles) {
            load_kv(jt & 1, jt + 2);
            CP_COMMIT();
        }
    }

    float inv0 = 1.f / lrow0, inv1 = 1.f / lrow1;
    size_t base0 = ((size_t)(b * S_LEN) + r0) * DM + h * 64;
    size_t base1 = ((size_t)(b * S_LEN) + r1) * DM + h * 64;
#pragma unroll
    for (int n = 0; n < 8; n++) {
        *(__half2*)(Ch_g + base0 + n * 8 + qc) = __floats2half2_rn(o[n][0] * inv0, o[n][1] * inv0);
        *(__half2*)(Ch_g + base1 + n * 8 + qc) = __floats2half2_rn(o[n][2] * inv1, o[n][3] * inv1);
    }
}

// ---------------------------------------------------------------------------
extern "C" void kernel_launch(void* const* d_in, const int* in_sizes, int n_in,
                              void* d_out, int out_size)
{
    (void)in_sizes; (void)n_in; (void)out_size;
    const float* x  = (const float*)d_in[0];
    const float* Wq = (const float*)d_in[2];
    const float* bq = (const float*)d_in[3];
    const float* Wk = (const float*)d_in[4];
    const float* bk = (const float*)d_in[5];
    const float* Wv = (const float*)d_in[6];
    const float* bv = (const float*)d_in[7];
    const float* Wo = (const float*)d_in[8];
    const float* bo = (const float*)d_in[9];
    float* out = (float*)d_out;

    __half *xh, *Qh, *Kh, *Vth, *Ch, *Wcat, *Woh;
    float* bcat;
    cudaGetSymbolAddress((void**)&xh, g_xh);
    cudaGetSymbolAddress((void**)&Qh, g_Qh);
    cudaGetSymbolAddress((void**)&Kh, g_Kh);
    cudaGetSymbolAddress((void**)&Vth, g_Vth);
    cudaGetSymbolAddress((void**)&Ch, g_Ch);
    cudaGetSymbolAddress((void**)&Wcat, g_Wcat);
    cudaGetSymbolAddress((void**)&Woh, g_Woh);
    cudaGetSymbolAddress((void**)&bcat, g_bcat);

    cudaFuncSetAttribute(gemm_fp16,
                         cudaFuncAttributeMaxDynamicSharedMemorySize, GEMM_SMEM);
    cudaFuncSetAttribute(gqa_flash_fp16,
                         cudaFuncAttributeMaxDynamicSharedMemorySize, FL_SMEM);

    const int NX = MROWS * DM;

    // prep
    conv_half<<<NX / 4 / 256, 256>>>(x, xh, NX);
    transpose_half<<<dim3(DM / 32,  DM / 32), dim3(32, 8)>>>(Wq, Wcat, DM, DM);
    transpose_half<<<dim3(KVW / 32, DM / 32), dim3(32, 8)>>>(Wk, Wcat + 2048 * DM, DM, KVW);
    transpose_half<<<dim3(KVW / 32, DM / 32), dim3(32, 8)>>>(Wv, Wcat + 2560 * DM, DM, KVW);
    transpose_half<<<dim3(DM / 32,  DM / 32), dim3(32, 8)>>>(Wo, Woh, DM, DM);
    bias_concat<<<NCAT / 256, 256>>>(bq, bk, bv, bcat);

    // fused QKV projection (column-routed epilogue)
    gemm_fp16<<<dim3(NCAT / 128, MROWS / 128), 256, GEMM_SMEM>>>(
        xh, Wcat, bcat, nullptr, Qh, Kh, Vth, 1, NCAT, DM);

    // attention
    gqa_flash_fp16<<<dim3(S_LEN / 128, NH, B_SZ), 256, FL_SMEM>>>(
        Qh, Kh, Vth, Ch);

    // output projection (fp32 out)
    gemm_fp16<<<dim3(DM / 128, MROWS / 128), 256, GEMM_SMEM>>>(
        Ch, Woh, bo, out, nullptr, nullptr, nullptr, 0, DM, DM);
}